// round 5
// baseline (speedup 1.0000x reference)
#include <cuda_runtime.h>
#include <cuda_bf16.h>
#include <cstdint>
#include <cstddef>

// Problem constants
#define BB 4
#define SS 4096
#define DD 1024
#define HH 16
#define DK 64
#define MM (BB * SS)          // 16384

// ---------------- scratch (device globals; no runtime allocation) ----------
__device__ float g_Q[(size_t)MM * DD];
__device__ float g_K[(size_t)MM * DD];
__device__ float g_V[(size_t)MM * DD];

__device__ __nv_bfloat16 g_q_hi[(size_t)MM * DD];
__device__ __nv_bfloat16 g_q_lo[(size_t)MM * DD];
__device__ __nv_bfloat16 g_k_hi[(size_t)MM * DD];
__device__ __nv_bfloat16 g_k_lo[(size_t)MM * DD];
__device__ __nv_bfloat16 g_v_hi[(size_t)MM * DD];
__device__ __nv_bfloat16 g_v_lo[(size_t)MM * DD];
__device__ __nv_bfloat16 g_a_hi[(size_t)MM * DD];
__device__ __nv_bfloat16 g_a_lo[(size_t)MM * DD];

__device__ __nv_bfloat16 g_wq_hi[(size_t)DD * DD];
__device__ __nv_bfloat16 g_wq_lo[(size_t)DD * DD];
__device__ __nv_bfloat16 g_wk_hi[(size_t)DD * DD];
__device__ __nv_bfloat16 g_wk_lo[(size_t)DD * DD];
__device__ __nv_bfloat16 g_wv_hi[(size_t)DD * DD];
__device__ __nv_bfloat16 g_wv_lo[(size_t)DD * DD];
__device__ __nv_bfloat16 g_wo_hi[(size_t)DD * DD];
__device__ __nv_bfloat16 g_wo_lo[(size_t)DD * DD];

#define KV_SPLIT 8
__device__ float g_KVp[(size_t)KV_SPLIT * 64 * DK * DK];
__device__ float g_KSp[(size_t)KV_SPLIT * 64 * DK];
__device__ float g_KV[(size_t)64 * DK * DK];
__device__ float g_KS[(size_t)64 * DK];

// ============================ PTX helpers ==================================
__device__ __forceinline__ uint32_t s2u(const void* p) {
    uint32_t a;
    asm("{ .reg .u64 t; cvta.to.shared.u64 t, %1; cvt.u32.u64 %0, t; }"
        : "=r"(a) : "l"(p));
    return a;
}

__device__ __forceinline__ void cp16(uint32_t dst, const void* src) {
    asm volatile("cp.async.cg.shared.global [%0], [%1], 16;"
                 :: "r"(dst), "l"(src) : "memory");
}

#define LDSM4(r, addr)                                                         \
    asm volatile("ldmatrix.sync.aligned.m8n8.x4.shared.b16 "                   \
                 "{%0,%1,%2,%3}, [%4];"                                        \
                 : "=r"((r)[0]), "=r"((r)[1]), "=r"((r)[2]), "=r"((r)[3])      \
                 : "r"(addr))

#define MMA16816(d, a, b)                                                      \
    asm volatile("mma.sync.aligned.m16n8k16.row.col.f32.bf16.bf16.f32 "        \
                 "{%0,%1,%2,%3}, {%4,%5,%6,%7}, {%8,%9}, {%0,%1,%2,%3};"       \
                 : "+f"((d)[0]), "+f"((d)[1]), "+f"((d)[2]), "+f"((d)[3])      \
                 : "r"((a)[0]), "r"((a)[1]), "r"((a)[2]), "r"((a)[3]),         \
                   "r"((b)[0]), "r"((b)[1]))

// ============================ split kernel =================================
__global__ void __launch_bounds__(256)
split_fp32(const float* __restrict__ x, __nv_bfloat16* __restrict__ hi,
           __nv_bfloat16* __restrict__ lo, int n4)
{
    int i = blockIdx.x * blockDim.x + threadIdx.x;
    if (i >= n4) return;
    float4 v = ((const float4*)x)[i];
    float f[4] = {v.x, v.y, v.z, v.w};
    __nv_bfloat16 h[4], l[4];
#pragma unroll
    for (int j = 0; j < 4; j++) {
        h[j] = __float2bfloat16(f[j]);
        l[j] = __float2bfloat16(f[j] - __bfloat162float(h[j]));
    }
    __nv_bfloat162* hp = (__nv_bfloat162*)hi;
    __nv_bfloat162* lp = (__nv_bfloat162*)lo;
    hp[2 * i]     = __halves2bfloat162(h[0], h[1]);
    hp[2 * i + 1] = __halves2bfloat162(h[2], h[3]);
    lp[2 * i]     = __halves2bfloat162(l[0], l[1]);
    lp[2 * i + 1] = __halves2bfloat162(l[2], l[3]);
}

// ============================ mma.sync GEMM ================================
// C[m,n] = sum_k A[m,k]*W[n,k], fp32 via split-bf16 (hi/lo), 3 MMA products.
// Multiple independent GEMMs via blockIdx.z.
// mode: 0 = plain, 1 = phi (elu+1), 2 = +bias
#define TM 128
#define TN 128
#define BKE 64                      // k elems per stage
#define KCH (DD / BKE)              // 16 chunks
#define RS 144                      // smem row stride bytes (128 data + 16 pad)
#define SPLIT_B (128 * RS)          // 18432
#define STAGE_B (4 * SPLIT_B)       // 73728
#define GSMEM (2 * STAGE_B)         // 147456

struct GemmArgs {
    const __nv_bfloat16* Ah[3];
    const __nv_bfloat16* Al[3];
    const __nv_bfloat16* Bh[3];
    const __nv_bfloat16* Bl[3];
    const float* bias[3];
    float* C[3];
    int mode[3];
};

__global__ void __launch_bounds__(256)
gemm_mma(GemmArgs p)
{
    extern __shared__ char smem[];
    const uint32_t sb = s2u(smem);
    const int tid = threadIdx.x;
    const int lane = tid & 31;
    const int warp = tid >> 5;
    const int wm = warp & 3;        // 32-row slab
    const int wn = warp >> 2;       // 64-col slab
    const int z = blockIdx.z;
    const int bm = blockIdx.y * TM;
    const int bn = blockIdx.x * TN;
    const int mode = p.mode[z];

    const __nv_bfloat16* gsrc[4];
    gsrc[0] = p.Ah[z] + (size_t)bm * DD;
    gsrc[1] = p.Al[z] + (size_t)bm * DD;
    gsrc[2] = p.Bh[z] + (size_t)bn * DD;
    gsrc[3] = p.Bl[z] + (size_t)bn * DD;

    auto produce = [&](int c) {
        const uint32_t st = sb + (uint32_t)(c & 1) * STAGE_B;
#pragma unroll
        for (int it = 0; it < 16; it++) {
            const int li  = it * 256 + tid;     // 0..4095
            const int s   = li >> 10;           // split 0..3
            const int idx = li & 1023;
            const int r   = idx >> 3;           // row 0..127
            const int seg = idx & 7;            // 16B segment
            cp16(st + (uint32_t)(s * SPLIT_B + r * RS + seg * 16),
                 gsrc[s] + (size_t)r * DD + c * BKE + seg * 8);
        }
        asm volatile("cp.async.commit_group;" ::: "memory");
    };

    float acc[2][8][4];
#pragma unroll
    for (int i = 0; i < 2; i++)
#pragma unroll
        for (int j = 0; j < 8; j++)
#pragma unroll
            for (int k = 0; k < 4; k++) acc[i][j][k] = 0.0f;

    // double-buffered fragments
    uint32_t ah[2][2][4], al[2][2][4], bh[2][8][2], bl[2][8][2];

    auto load_frags = [&](int buf, uint32_t st, int step) {
#pragma unroll
        for (int mt = 0; mt < 2; mt++) {
            const int row = wm * 32 + mt * 16 + (lane & 15);
            const uint32_t off =
                (uint32_t)(row * RS + step * 32 + ((lane >> 4) & 1) * 16);
            LDSM4(ah[buf][mt], st + off);
            LDSM4(al[buf][mt], st + SPLIT_B + off);
        }
#pragma unroll
        for (int nt2 = 0; nt2 < 4; nt2++) {
            // B tile is [N,K] row-major (k contiguous) -> non-trans ldmatrix
            const int nrow = wn * 64 + nt2 * 16 + (lane & 7) + ((lane >> 4) & 1) * 8;
            const uint32_t off =
                (uint32_t)(nrow * RS + step * 32 + ((lane >> 3) & 1) * 16);
            uint32_t r[4];
            LDSM4(r, st + 2 * SPLIT_B + off);
            bh[buf][nt2 * 2][0] = r[0]; bh[buf][nt2 * 2][1] = r[1];
            bh[buf][nt2 * 2 + 1][0] = r[2]; bh[buf][nt2 * 2 + 1][1] = r[3];
            LDSM4(r, st + 3 * SPLIT_B + off);
            bl[buf][nt2 * 2][0] = r[0]; bl[buf][nt2 * 2][1] = r[1];
            bl[buf][nt2 * 2 + 1][0] = r[2]; bl[buf][nt2 * 2 + 1][1] = r[3];
        }
    };

    produce(0);

    for (int c = 0; c < KCH; c++) {
        asm volatile("cp.async.wait_group 0;" ::: "memory");
        __syncthreads();
        if (c + 1 < KCH) produce(c + 1);   // overlaps entire chunk compute

        const uint32_t st = sb + (uint32_t)(c & 1) * STAGE_B;
        load_frags(0, st, 0);
#pragma unroll
        for (int step = 0; step < 4; step++) {
            if (step < 3) load_frags((step + 1) & 1, st, step + 1);
            const int b = step & 1;
#pragma unroll
            for (int mt = 0; mt < 2; mt++)
#pragma unroll
                for (int nt = 0; nt < 8; nt++) {
                    MMA16816(acc[mt][nt], ah[b][mt], bh[b][nt]);
                    MMA16816(acc[mt][nt], ah[b][mt], bl[b][nt]);
                    MMA16816(acc[mt][nt], al[b][mt], bh[b][nt]);
                }
        }
    }

    // epilogue
    float* C = p.C[z];
    const int gr = lane >> 2;        // 0..7
    const int gc = (lane & 3) * 2;   // 0,2,4,6
#pragma unroll
    for (int mt = 0; mt < 2; mt++) {
#pragma unroll
        for (int nt = 0; nt < 8; nt++) {
            const int row0 = bm + wm * 32 + mt * 16 + gr;
            const int col  = bn + wn * 64 + nt * 8 + gc;
            float v[4] = {acc[mt][nt][0], acc[mt][nt][1],
                          acc[mt][nt][2], acc[mt][nt][3]};
            if (mode == 1) {
#pragma unroll
                for (int j = 0; j < 4; j++)
                    v[j] = (v[j] > 0.0f) ? (v[j] + 1.0f) : expf(v[j]);
            } else if (mode == 2) {
                const float b0 = p.bias[z][col], b1 = p.bias[z][col + 1];
                v[0] += b0; v[1] += b1; v[2] += b0; v[3] += b1;
            }
            float2 p0; p0.x = v[0]; p0.y = v[1];
            float2 p1; p1.x = v[2]; p1.y = v[3];
            *(float2*)(C + (size_t)row0 * DD + col) = p0;
            *(float2*)(C + (size_t)(row0 + 8) * DD + col) = p1;
        }
    }
}

// ---------------- KV accumulation: KV[bh] = sum_s k(s) outer v(s) ----------
__global__ void __launch_bounds__(256)
kv_kernel(const float* __restrict__ Kp, const float* __restrict__ Vp,
          float* __restrict__ KVp, float* __restrict__ KSp)
{
    const int bh = blockIdx.x;          // 0..63
    const int sp = blockIdx.y;          // 0..KV_SPLIT-1
    const int b = bh >> 4, h = bh & 15;
    const int tid = threadIdx.x;
    const int w = tid >> 5, lane = tid & 31;
    const int tx = tid & 15;
    const int ty = tid >> 4;

    __shared__ float ks[8][64];
    __shared__ float vs[8][64];

    float acc[4][4];
#pragma unroll
    for (int i = 0; i < 4; i++)
#pragma unroll
        for (int j = 0; j < 4; j++) acc[i][j] = 0.0f;
    float kacc = 0.0f;

    const int sPer = SS / KV_SPLIT;
    const int sBase = sp * sPer;

    for (int s0 = 0; s0 < sPer; s0 += 8) {
        size_t row = ((size_t)(b * SS + sBase + s0 + w)) * DD + h * DK;
        ks[w][lane]      = Kp[row + lane];
        ks[w][lane + 32] = Kp[row + lane + 32];
        vs[w][lane]      = Vp[row + lane];
        vs[w][lane + 32] = Vp[row + lane + 32];
        __syncthreads();

        if (tid < 64) {
#pragma unroll
            for (int j = 0; j < 8; j++) kacc += ks[j][tid];
        }
#pragma unroll
        for (int j = 0; j < 8; j++) {
            float4 av = *(const float4*)&ks[j][ty * 4];
            float4 bv = *(const float4*)&vs[j][tx * 4];
            float a[4] = {av.x, av.y, av.z, av.w};
            float c[4] = {bv.x, bv.y, bv.z, bv.w};
#pragma unroll
            for (int i = 0; i < 4; i++)
#pragma unroll
                for (int jj = 0; jj < 4; jj++)
                    acc[i][jj] += a[i] * c[jj];
        }
        __syncthreads();
    }

    float* outp = KVp + ((size_t)(sp * 64 + bh)) * (DK * DK);
#pragma unroll
    for (int i = 0; i < 4; i++)
#pragma unroll
        for (int jj = 0; jj < 4; jj++)
            outp[(ty * 4 + i) * DK + tx * 4 + jj] = acc[i][jj];

    if (tid < 64)
        KSp[((size_t)(sp * 64 + bh)) * DK + tid] = kacc;
}

__global__ void kv_reduce(const float* __restrict__ KVp, const float* __restrict__ KSp,
                          float* __restrict__ KV, float* __restrict__ KS)
{
    const int bh = blockIdx.x;
    const int tid = threadIdx.x;
    for (int e = tid; e < DK * DK; e += 256) {
        float s = 0.0f;
#pragma unroll
        for (int r = 0; r < KV_SPLIT; r++)
            s += KVp[((size_t)(r * 64 + bh)) * (DK * DK) + e];
        KV[(size_t)bh * (DK * DK) + e] = s;
    }
    if (tid < DK) {
        float s = 0.0f;
#pragma unroll
        for (int r = 0; r < KV_SPLIT; r++)
            s += KSp[((size_t)(r * 64 + bh)) * DK + tid];
        KS[(size_t)bh * DK + tid] = s;
    }
}

// ---------------- attention normalize -> split-bf16 output -----------------
__global__ void __launch_bounds__(256)
attn_kernel(const float* __restrict__ Q, const float* __restrict__ KV,
            const float* __restrict__ KS,
            __nv_bfloat16* __restrict__ Ahi, __nv_bfloat16* __restrict__ Alo)
{
    const int bh = blockIdx.x;
    const int sc = blockIdx.y;
    const int b = bh >> 4, h = bh & 15;
    const int tid = threadIdx.x;

    __shared__ float KVs[DK * DK];
    __shared__ float KSs[DK];
    __shared__ float qs[4][DK];

    for (int e = tid; e < DK * DK; e += 256)
        KVs[e] = KV[(size_t)bh * (DK * DK) + e];
    if (tid < DK) KSs[tid] = KS[(size_t)bh * DK + tid];
    __syncthreads();

    const int ssub = tid >> 6;
    const int de = tid & 63;

    for (int it = 0; it < 32; it++) {
        const int s = sc * 128 + it * 4 + ssub;
        const size_t row = ((size_t)(b * SS + s)) * DD + h * DK;
        qs[ssub][de] = Q[row + de];
        __syncthreads();

        float num = 0.0f, den = 0.0f;
#pragma unroll
        for (int dk = 0; dk < DK; dk++) {
            const float q = qs[ssub][dk];
            num += q * KVs[dk * DK + de];
            den += q * KSs[dk];
        }
        float o = num / (den + 1e-6f);
        __nv_bfloat16 hv = __float2bfloat16(o);
        Ahi[row + de] = hv;
        Alo[row + de] = __float2bfloat16(o - __bfloat162float(hv));
        __syncthreads();
    }
}

// ---------------- launch ---------------------------------------------------
extern "C" void kernel_launch(void* const* d_in, const int* in_sizes, int n_in,
                              void* d_out, int out_size)
{
    const float* query = (const float*)d_in[0];
    const float* key   = (const float*)d_in[1];
    const float* value = (const float*)d_in[2];
    const float* Wq    = (const float*)d_in[3];
    const float* Wk    = (const float*)d_in[4];
    const float* Wv    = (const float*)d_in[5];
    const float* Wo    = (const float*)d_in[6];
    const float* bo    = (const float*)d_in[7];
    float* out = (float*)d_out;

    float *gQ, *gK, *gV, *gKVp, *gKSp, *gKV, *gKS;
    __nv_bfloat16 *qh, *ql, *kh, *kl, *vh, *vl, *ah, *al;
    __nv_bfloat16 *wqh, *wql, *wkh, *wkl, *wvh, *wvl, *woh, *wol;
    cudaGetSymbolAddress((void**)&gQ,  g_Q);
    cudaGetSymbolAddress((void**)&gK,  g_K);
    cudaGetSymbolAddress((void**)&gV,  g_V);
    cudaGetSymbolAddress((void**)&gKVp, g_KVp);
    cudaGetSymbolAddress((void**)&gKSp, g_KSp);
    cudaGetSymbolAddress((void**)&gKV, g_KV);
    cudaGetSymbolAddress((void**)&gKS, g_KS);
    cudaGetSymbolAddress((void**)&qh, g_q_hi);
    cudaGetSymbolAddress((void**)&ql, g_q_lo);
    cudaGetSymbolAddress((void**)&kh, g_k_hi);
    cudaGetSymbolAddress((void**)&kl, g_k_lo);
    cudaGetSymbolAddress((void**)&vh, g_v_hi);
    cudaGetSymbolAddress((void**)&vl, g_v_lo);
    cudaGetSymbolAddress((void**)&ah, g_a_hi);
    cudaGetSymbolAddress((void**)&al, g_a_lo);
    cudaGetSymbolAddress((void**)&wqh, g_wq_hi);
    cudaGetSymbolAddress((void**)&wql, g_wq_lo);
    cudaGetSymbolAddress((void**)&wkh, g_wk_hi);
    cudaGetSymbolAddress((void**)&wkl, g_wk_lo);
    cudaGetSymbolAddress((void**)&wvh, g_wv_hi);
    cudaGetSymbolAddress((void**)&wvl, g_wv_lo);
    cudaGetSymbolAddress((void**)&woh, g_wo_hi);
    cudaGetSymbolAddress((void**)&wol, g_wo_lo);

    cudaFuncSetAttribute(gemm_mma, cudaFuncAttributeMaxDynamicSharedMemorySize,
                         GSMEM);

    const int nAct4 = (MM * DD) / 4;
    const int nW4   = (DD * DD) / 4;
    split_fp32<<<nAct4 / 256, 256>>>(query, qh, ql, nAct4);
    split_fp32<<<nAct4 / 256, 256>>>(key,   kh, kl, nAct4);
    split_fp32<<<nAct4 / 256, 256>>>(value, vh, vl, nAct4);
    split_fp32<<<nW4 / 256, 256>>>(Wq, wqh, wql, nW4);
    split_fp32<<<nW4 / 256, 256>>>(Wk, wkh, wkl, nW4);
    split_fp32<<<nW4 / 256, 256>>>(Wv, wvh, wvl, nW4);
    split_fp32<<<nW4 / 256, 256>>>(Wo, woh, wol, nW4);

    // fused Q/K/V projections (z = 0,1,2)
    GemmArgs aq;
    aq.Ah[0] = qh; aq.Al[0] = ql; aq.Bh[0] = wqh; aq.Bl[0] = wql;
    aq.C[0] = gQ; aq.bias[0] = bo; aq.mode[0] = 1;
    aq.Ah[1] = kh; aq.Al[1] = kl; aq.Bh[1] = wkh; aq.Bl[1] = wkl;
    aq.C[1] = gK; aq.bias[1] = bo; aq.mode[1] = 1;
    aq.Ah[2] = vh; aq.Al[2] = vl; aq.Bh[2] = wvh; aq.Bl[2] = wvl;
    aq.C[2] = gV; aq.bias[2] = bo; aq.mode[2] = 0;

    dim3 gqkv(DD / TN, MM / TM, 3);   // (8, 128, 3)
    gemm_mma<<<gqkv, 256, GSMEM>>>(aq);

    kv_kernel<<<dim3(64, KV_SPLIT), 256>>>(gK, gV, gKVp, gKSp);
    kv_reduce<<<64, 256>>>(gKVp, gKSp, gKV, gKS);
    attn_kernel<<<dim3(64, 32), 256>>>(gQ, gKV, gKS, ah, al);

    // output projection (+bias)
    GemmArgs ao;
    ao.Ah[0] = ah; ao.Al[0] = al; ao.Bh[0] = woh; ao.Bl[0] = wol;
    ao.C[0] = out; ao.bias[0] = bo; ao.mode[0] = 2;
    ao.Ah[1] = ah; ao.Al[1] = al; ao.Bh[1] = woh; ao.Bl[1] = wol;
    ao.C[1] = out; ao.bias[1] = bo; ao.mode[1] = 2;
    ao.Ah[2] = ah; ao.Al[2] = al; ao.Bh[2] = woh; ao.Bl[2] = wol;
    ao.C[2] = out; ao.bias[2] = bo; ao.mode[2] = 2;

    dim3 go(DD / TN, MM / TM, 1);     // (8, 128, 1)
    gemm_mma<<<go, 256, GSMEM>>>(ao);
}

// round 6
// speedup vs baseline: 1.1293x; 1.1293x over previous
#include <cuda_runtime.h>
#include <cuda_bf16.h>
#include <cstdint>
#include <cstddef>

// Problem constants
#define BB 4
#define SS 4096
#define DD 1024
#define HH 16
#define DK 64
#define MM (BB * SS)          // 16384

// ---------------- scratch (device globals; no runtime allocation) ----------
__device__ float g_Q[(size_t)MM * DD];
__device__ float g_K[(size_t)MM * DD];
__device__ float g_V[(size_t)MM * DD];

__device__ __nv_bfloat16 g_q_hi[(size_t)MM * DD];
__device__ __nv_bfloat16 g_q_lo[(size_t)MM * DD];
__device__ __nv_bfloat16 g_k_hi[(size_t)MM * DD];
__device__ __nv_bfloat16 g_k_lo[(size_t)MM * DD];
__device__ __nv_bfloat16 g_v_hi[(size_t)MM * DD];
__device__ __nv_bfloat16 g_v_lo[(size_t)MM * DD];
__device__ __nv_bfloat16 g_a_hi[(size_t)MM * DD];
__device__ __nv_bfloat16 g_a_lo[(size_t)MM * DD];

__device__ __nv_bfloat16 g_wq_hi[(size_t)DD * DD];
__device__ __nv_bfloat16 g_wq_lo[(size_t)DD * DD];
__device__ __nv_bfloat16 g_wk_hi[(size_t)DD * DD];
__device__ __nv_bfloat16 g_wk_lo[(size_t)DD * DD];
__device__ __nv_bfloat16 g_wv_hi[(size_t)DD * DD];
__device__ __nv_bfloat16 g_wv_lo[(size_t)DD * DD];
__device__ __nv_bfloat16 g_wo_hi[(size_t)DD * DD];
__device__ __nv_bfloat16 g_wo_lo[(size_t)DD * DD];

#define KV_SPLIT 32
__device__ float g_KVp[(size_t)KV_SPLIT * 64 * DK * DK];
__device__ float g_KSp[(size_t)KV_SPLIT * 64 * DK];
__device__ float g_KV[(size_t)64 * DK * DK];
__device__ float g_KS[(size_t)64 * DK];

// ============================ PTX helpers ==================================
__device__ __forceinline__ uint32_t s2u(const void* p) {
    uint32_t a;
    asm("{ .reg .u64 t; cvta.to.shared.u64 t, %1; cvt.u32.u64 %0, t; }"
        : "=r"(a) : "l"(p));
    return a;
}

__device__ __forceinline__ void cp16(uint32_t dst, const void* src) {
    asm volatile("cp.async.cg.shared.global [%0], [%1], 16;"
                 :: "r"(dst), "l"(src) : "memory");
}

#define LDSM4(r, addr)                                                         \
    asm volatile("ldmatrix.sync.aligned.m8n8.x4.shared.b16 "                   \
                 "{%0,%1,%2,%3}, [%4];"                                        \
                 : "=r"((r)[0]), "=r"((r)[1]), "=r"((r)[2]), "=r"((r)[3])      \
                 : "r"(addr))

#define MMA16816(d, a, b)                                                      \
    asm volatile("mma.sync.aligned.m16n8k16.row.col.f32.bf16.bf16.f32 "        \
                 "{%0,%1,%2,%3}, {%4,%5,%6,%7}, {%8,%9}, {%0,%1,%2,%3};"       \
                 : "+f"((d)[0]), "+f"((d)[1]), "+f"((d)[2]), "+f"((d)[3])      \
                 : "r"((a)[0]), "r"((a)[1]), "r"((a)[2]), "r"((a)[3]),         \
                   "r"((b)[0]), "r"((b)[1]))

// ============================ split kernel =================================
// 4 independent float4 chains per thread (MLP=4; round-5 ncu: issue=16%, MLP=1)
__global__ void __launch_bounds__(256)
split_fp32(const float* __restrict__ x, __nv_bfloat16* __restrict__ hi,
           __nv_bfloat16* __restrict__ lo, int n4)
{
    const int stride = n4 >> 2;
    int i0 = blockIdx.x * blockDim.x + threadIdx.x;
    if (i0 >= stride) return;
    float4 v[4];
#pragma unroll
    for (int c = 0; c < 4; c++) v[c] = ((const float4*)x)[i0 + c * stride];
#pragma unroll
    for (int c = 0; c < 4; c++) {
        const int i = i0 + c * stride;
        float f[4] = {v[c].x, v[c].y, v[c].z, v[c].w};
        __nv_bfloat16 h[4], l[4];
#pragma unroll
        for (int j = 0; j < 4; j++) {
            h[j] = __float2bfloat16(f[j]);
            l[j] = __float2bfloat16(f[j] - __bfloat162float(h[j]));
        }
        __nv_bfloat162* hp = (__nv_bfloat162*)hi;
        __nv_bfloat162* lp = (__nv_bfloat162*)lo;
        hp[2 * i]     = __halves2bfloat162(h[0], h[1]);
        hp[2 * i + 1] = __halves2bfloat162(h[2], h[3]);
        lp[2 * i]     = __halves2bfloat162(l[0], l[1]);
        lp[2 * i + 1] = __halves2bfloat162(l[2], l[3]);
    }
}

// ============================ mma.sync GEMM ================================
// C[m,n] = sum_k A[m,k]*W[n,k], fp32 via split-bf16 (hi/lo), 3 MMA products.
// PRODUCT-MAJOR inner ordering: 16 independent MMAs between accumulator reuse.
// mode: 0 = plain, 1 = phi (elu+1), 2 = +bias
#define TM 128
#define TN 128
#define BKE 64                      // k elems per stage
#define KCH (DD / BKE)              // 16 chunks
#define RS 144                      // smem row stride bytes (128 data + 16 pad)
#define SPLIT_B (128 * RS)          // 18432
#define STAGE_B (4 * SPLIT_B)       // 73728
#define GSMEM (2 * STAGE_B)         // 147456

struct GemmArgs {
    const __nv_bfloat16* Ah[3];
    const __nv_bfloat16* Al[3];
    const __nv_bfloat16* Bh[3];
    const __nv_bfloat16* Bl[3];
    const float* bias[3];
    float* C[3];
    int mode[3];
};

__global__ void __launch_bounds__(256)
gemm_mma(GemmArgs p)
{
    extern __shared__ char smem[];
    const uint32_t sb = s2u(smem);
    const int tid = threadIdx.x;
    const int lane = tid & 31;
    const int warp = tid >> 5;
    const int wm = warp & 3;        // 32-row slab
    const int wn = warp >> 2;       // 64-col slab
    const int z = blockIdx.z;
    const int bm = blockIdx.y * TM;
    const int bn = blockIdx.x * TN;
    const int mode = p.mode[z];

    const __nv_bfloat16* gsrc[4];
    gsrc[0] = p.Ah[z] + (size_t)bm * DD;
    gsrc[1] = p.Al[z] + (size_t)bm * DD;
    gsrc[2] = p.Bh[z] + (size_t)bn * DD;
    gsrc[3] = p.Bl[z] + (size_t)bn * DD;

    auto produce = [&](int c) {
        const uint32_t st = sb + (uint32_t)(c & 1) * STAGE_B;
#pragma unroll
        for (int it = 0; it < 16; it++) {
            const int li  = it * 256 + tid;     // 0..4095
            const int s   = li >> 10;           // split 0..3
            const int idx = li & 1023;
            const int r   = idx >> 3;           // row 0..127
            const int seg = idx & 7;            // 16B segment
            cp16(st + (uint32_t)(s * SPLIT_B + r * RS + seg * 16),
                 gsrc[s] + (size_t)r * DD + c * BKE + seg * 8);
        }
        asm volatile("cp.async.commit_group;" ::: "memory");
    };

    float acc[2][8][4];
#pragma unroll
    for (int i = 0; i < 2; i++)
#pragma unroll
        for (int j = 0; j < 8; j++)
#pragma unroll
            for (int k = 0; k < 4; k++) acc[i][j][k] = 0.0f;

    produce(0);

    for (int c = 0; c < KCH; c++) {
        asm volatile("cp.async.wait_group 0;" ::: "memory");
        __syncthreads();
        if (c + 1 < KCH) produce(c + 1);   // overlaps entire chunk compute

        const uint32_t st = sb + (uint32_t)(c & 1) * STAGE_B;
#pragma unroll
        for (int step = 0; step < 4; step++) {
            uint32_t ah[2][4], al[2][4], bh[8][2], bl[8][2];
#pragma unroll
            for (int mt = 0; mt < 2; mt++) {
                const int row = wm * 32 + mt * 16 + (lane & 15);
                const uint32_t off =
                    (uint32_t)(row * RS + step * 32 + ((lane >> 4) & 1) * 16);
                LDSM4(ah[mt], st + off);
                LDSM4(al[mt], st + SPLIT_B + off);
            }
#pragma unroll
            for (int nt2 = 0; nt2 < 4; nt2++) {
                // B tile is [N,K] row-major (k contiguous) -> non-trans ldmatrix
                const int nrow = wn * 64 + nt2 * 16 + (lane & 7) + ((lane >> 4) & 1) * 8;
                const uint32_t off =
                    (uint32_t)(nrow * RS + step * 32 + ((lane >> 3) & 1) * 16);
                uint32_t r[4];
                LDSM4(r, st + 2 * SPLIT_B + off);
                bh[nt2 * 2][0] = r[0]; bh[nt2 * 2][1] = r[1];
                bh[nt2 * 2 + 1][0] = r[2]; bh[nt2 * 2 + 1][1] = r[3];
                LDSM4(r, st + 3 * SPLIT_B + off);
                bl[nt2 * 2][0] = r[0]; bl[nt2 * 2][1] = r[1];
                bl[nt2 * 2 + 1][0] = r[2]; bl[nt2 * 2 + 1][1] = r[3];
            }
            // product-major: same accumulator touched every 16 MMAs, not 3x back-to-back
#pragma unroll
            for (int mt = 0; mt < 2; mt++)
#pragma unroll
                for (int nt = 0; nt < 8; nt++)
                    MMA16816(acc[mt][nt], ah[mt], bh[nt]);
#pragma unroll
            for (int mt = 0; mt < 2; mt++)
#pragma unroll
                for (int nt = 0; nt < 8; nt++)
                    MMA16816(acc[mt][nt], ah[mt], bl[nt]);
#pragma unroll
            for (int mt = 0; mt < 2; mt++)
#pragma unroll
                for (int nt = 0; nt < 8; nt++)
                    MMA16816(acc[mt][nt], al[mt], bh[nt]);
        }
    }

    // epilogue
    float* C = p.C[z];
    const int gr = lane >> 2;        // 0..7
    const int gc = (lane & 3) * 2;   // 0,2,4,6
#pragma unroll
    for (int mt = 0; mt < 2; mt++) {
#pragma unroll
        for (int nt = 0; nt < 8; nt++) {
            const int row0 = bm + wm * 32 + mt * 16 + gr;
            const int col  = bn + wn * 64 + nt * 8 + gc;
            float v[4] = {acc[mt][nt][0], acc[mt][nt][1],
                          acc[mt][nt][2], acc[mt][nt][3]};
            if (mode == 1) {
#pragma unroll
                for (int j = 0; j < 4; j++)
                    v[j] = (v[j] > 0.0f) ? (v[j] + 1.0f) : expf(v[j]);
            } else if (mode == 2) {
                const float b0 = p.bias[z][col], b1 = p.bias[z][col + 1];
                v[0] += b0; v[1] += b1; v[2] += b0; v[3] += b1;
            }
            float2 p0; p0.x = v[0]; p0.y = v[1];
            float2 p1; p1.x = v[2]; p1.y = v[3];
            *(float2*)(C + (size_t)row0 * DD + col) = p0;
            *(float2*)(C + (size_t)(row0 + 8) * DD + col) = p1;
        }
    }
}

// ---------------- KV accumulation: KV[bh] = sum_s k(s) outer v(s) ----------
// KV_SPLIT=32 (2048 CTAs), float4-vectorized loads.
__global__ void __launch_bounds__(256)
kv_kernel(const float* __restrict__ Kp, const float* __restrict__ Vp,
          float* __restrict__ KVp, float* __restrict__ KSp)
{
    const int bh = blockIdx.x;          // 0..63
    const int sp = blockIdx.y;          // 0..KV_SPLIT-1
    const int b = bh >> 4, h = bh & 15;
    const int tid = threadIdx.x;
    const int tx = tid & 15;
    const int ty = tid >> 4;

    __shared__ float ks[8][68];
    __shared__ float vs[8][68];

    float acc[4][4];
#pragma unroll
    for (int i = 0; i < 4; i++)
#pragma unroll
        for (int j = 0; j < 4; j++) acc[i][j] = 0.0f;
    float kacc = 0.0f;

    const int sPer = SS / KV_SPLIT;     // 128
    const int sBase = sp * sPer;

    const int lrow = (tid & 127) >> 4;  // 0..7
    const int lseg = tid & 15;          // 0..15

    for (int s0 = 0; s0 < sPer; s0 += 8) {
        const size_t gaddr =
            ((size_t)(b * SS + sBase + s0 + lrow)) * DD + h * DK + lseg * 4;
        if (tid < 128)
            *(float4*)&ks[lrow][lseg * 4] = *(const float4*)(Kp + gaddr);
        else
            *(float4*)&vs[lrow][lseg * 4] = *(const float4*)(Vp + gaddr);
        __syncthreads();

        if (tid < 64) {
#pragma unroll
            for (int j = 0; j < 8; j++) kacc += ks[j][tid];
        }
#pragma unroll
        for (int j = 0; j < 8; j++) {
            float4 av = *(const float4*)&ks[j][ty * 4];
            float4 bv = *(const float4*)&vs[j][tx * 4];
            float a[4] = {av.x, av.y, av.z, av.w};
            float c[4] = {bv.x, bv.y, bv.z, bv.w};
#pragma unroll
            for (int i = 0; i < 4; i++)
#pragma unroll
                for (int jj = 0; jj < 4; jj++)
                    acc[i][jj] += a[i] * c[jj];
        }
        __syncthreads();
    }

    float* outp = KVp + ((size_t)(sp * 64 + bh)) * (DK * DK);
#pragma unroll
    for (int i = 0; i < 4; i++)
#pragma unroll
        for (int jj = 0; jj < 4; jj++)
            outp[(ty * 4 + i) * DK + tx * 4 + jj] = acc[i][jj];

    if (tid < 64)
        KSp[((size_t)(sp * 64 + bh)) * DK + tid] = kacc;
}

__global__ void kv_reduce(const float* __restrict__ KVp, const float* __restrict__ KSp,
                          float* __restrict__ KV, float* __restrict__ KS)
{
    const int bh = blockIdx.x;
    const int tid = threadIdx.x;
    for (int e = tid; e < DK * DK; e += 256) {
        float s = 0.0f;
#pragma unroll
        for (int r = 0; r < KV_SPLIT; r++)
            s += KVp[((size_t)(r * 64 + bh)) * (DK * DK) + e];
        KV[(size_t)bh * (DK * DK) + e] = s;
    }
    if (tid < DK) {
        float s = 0.0f;
#pragma unroll
        for (int r = 0; r < KV_SPLIT; r++)
            s += KSp[((size_t)(r * 64 + bh)) * DK + tid];
        KS[(size_t)bh * DK + tid] = s;
    }
}

// ---------------- attention normalize -> split-bf16 output -----------------
// Warp-autonomous: per-warp q buffers, __syncwarp only, 8 rows in flight.
__global__ void __launch_bounds__(256)
attn_kernel(const float* __restrict__ Q, const float* __restrict__ KV,
            const float* __restrict__ KS,
            __nv_bfloat16* __restrict__ Ahi, __nv_bfloat16* __restrict__ Alo)
{
    const int bh = blockIdx.x;          // 0..63
    const int sc = blockIdx.y;          // 0..7 (512 rows per block)
    const int b = bh >> 4, h = bh & 15;
    const int tid = threadIdx.x;
    const int w = tid >> 5, l = tid & 31;

    __shared__ float KVs[DK * DK];
    __shared__ float KSs[DK];
    __shared__ float qb[8][8][64];      // [warp][row][dk]

    for (int i = tid; i < (DK * DK) / 4; i += 256)
        ((float4*)KVs)[i] = ((const float4*)(KV + (size_t)bh * DK * DK))[i];
    if (tid < DK) KSs[tid] = KS[(size_t)bh * DK + tid];
    __syncthreads();

    const size_t qbase = ((size_t)(b * SS) + sc * 512 + w * 64) * DD + h * DK;

    for (int g = 0; g < 8; g++) {
        const float* qrow = Q + qbase + (size_t)(g * 8) * DD;
#pragma unroll
        for (int t = 0; t < 4; t++) {
            const int idx = l + t * 32;           // 0..127
            const int r = idx >> 4, seg = idx & 15;
            *(float4*)&qb[w][r][seg * 4] =
                *(const float4*)(qrow + (size_t)r * DD + seg * 4);
        }
        __syncwarp();

        float n0[8], n1[8], dn[8];
#pragma unroll
        for (int r = 0; r < 8; r++) { n0[r] = 0.f; n1[r] = 0.f; dn[r] = 0.f; }
#pragma unroll
        for (int dk = 0; dk < DK; dk++) {
            const float kv0 = KVs[dk * DK + l];
            const float kv1 = KVs[dk * DK + l + 32];
            const float ksv = KSs[dk];
#pragma unroll
            for (int r = 0; r < 8; r++) {
                const float q = qb[w][r][dk];
                n0[r] += q * kv0;
                n1[r] += q * kv1;
                dn[r] += q * ksv;
            }
        }
#pragma unroll
        for (int r = 0; r < 8; r++) {
            const size_t orow = qbase + (size_t)(g * 8 + r) * DD;
            const float inv = 1.0f / (dn[r] + 1e-6f);
            const float o0 = n0[r] * inv;
            const float o1 = n1[r] * inv;
            const __nv_bfloat16 h0 = __float2bfloat16(o0);
            const __nv_bfloat16 h1 = __float2bfloat16(o1);
            Ahi[orow + l]      = h0;
            Ahi[orow + l + 32] = h1;
            Alo[orow + l]      = __float2bfloat16(o0 - __bfloat162float(h0));
            Alo[orow + l + 32] = __float2bfloat16(o1 - __bfloat162float(h1));
        }
        __syncwarp();
    }
}

// ---------------- launch ---------------------------------------------------
extern "C" void kernel_launch(void* const* d_in, const int* in_sizes, int n_in,
                              void* d_out, int out_size)
{
    const float* query = (const float*)d_in[0];
    const float* key   = (const float*)d_in[1];
    const float* value = (const float*)d_in[2];
    const float* Wq    = (const float*)d_in[3];
    const float* Wk    = (const float*)d_in[4];
    const float* Wv    = (const float*)d_in[5];
    const float* Wo    = (const float*)d_in[6];
    const float* bo    = (const float*)d_in[7];
    float* out = (float*)d_out;

    float *gQ, *gK, *gV, *gKVp, *gKSp, *gKV, *gKS;
    __nv_bfloat16 *qh, *ql, *kh, *kl, *vh, *vl, *ah, *al;
    __nv_bfloat16 *wqh, *wql, *wkh, *wkl, *wvh, *wvl, *woh, *wol;
    cudaGetSymbolAddress((void**)&gQ,  g_Q);
    cudaGetSymbolAddress((void**)&gK,  g_K);
    cudaGetSymbolAddress((void**)&gV,  g_V);
    cudaGetSymbolAddress((void**)&gKVp, g_KVp);
    cudaGetSymbolAddress((void**)&gKSp, g_KSp);
    cudaGetSymbolAddress((void**)&gKV, g_KV);
    cudaGetSymbolAddress((void**)&gKS, g_KS);
    cudaGetSymbolAddress((void**)&qh, g_q_hi);
    cudaGetSymbolAddress((void**)&ql, g_q_lo);
    cudaGetSymbolAddress((void**)&kh, g_k_hi);
    cudaGetSymbolAddress((void**)&kl, g_k_lo);
    cudaGetSymbolAddress((void**)&vh, g_v_hi);
    cudaGetSymbolAddress((void**)&vl, g_v_lo);
    cudaGetSymbolAddress((void**)&ah, g_a_hi);
    cudaGetSymbolAddress((void**)&al, g_a_lo);
    cudaGetSymbolAddress((void**)&wqh, g_wq_hi);
    cudaGetSymbolAddress((void**)&wql, g_wq_lo);
    cudaGetSymbolAddress((void**)&wkh, g_wk_hi);
    cudaGetSymbolAddress((void**)&wkl, g_wk_lo);
    cudaGetSymbolAddress((void**)&wvh, g_wv_hi);
    cudaGetSymbolAddress((void**)&wvl, g_wv_lo);
    cudaGetSymbolAddress((void**)&woh, g_wo_hi);
    cudaGetSymbolAddress((void**)&wol, g_wo_lo);

    cudaFuncSetAttribute(gemm_mma, cudaFuncAttributeMaxDynamicSharedMemorySize,
                         GSMEM);

    const int nAct4 = (MM * DD) / 4;
    const int nW4   = (DD * DD) / 4;
    split_fp32<<<nAct4 / 4 / 256, 256>>>(query, qh, ql, nAct4);
    split_fp32<<<nAct4 / 4 / 256, 256>>>(key,   kh, kl, nAct4);
    split_fp32<<<nAct4 / 4 / 256, 256>>>(value, vh, vl, nAct4);
    split_fp32<<<nW4 / 4 / 256, 256>>>(Wq, wqh, wql, nW4);
    split_fp32<<<nW4 / 4 / 256, 256>>>(Wk, wkh, wkl, nW4);
    split_fp32<<<nW4 / 4 / 256, 256>>>(Wv, wvh, wvl, nW4);
    split_fp32<<<nW4 / 4 / 256, 256>>>(Wo, woh, wol, nW4);

    // fused Q/K/V projections (z = 0,1,2)
    GemmArgs aq;
    aq.Ah[0] = qh; aq.Al[0] = ql; aq.Bh[0] = wqh; aq.Bl[0] = wql;
    aq.C[0] = gQ; aq.bias[0] = bo; aq.mode[0] = 1;
    aq.Ah[1] = kh; aq.Al[1] = kl; aq.Bh[1] = wkh; aq.Bl[1] = wkl;
    aq.C[1] = gK; aq.bias[1] = bo; aq.mode[1] = 1;
    aq.Ah[2] = vh; aq.Al[2] = vl; aq.Bh[2] = wvh; aq.Bl[2] = wvl;
    aq.C[2] = gV; aq.bias[2] = bo; aq.mode[2] = 0;

    dim3 gqkv(DD / TN, MM / TM, 3);   // (8, 128, 3)
    gemm_mma<<<gqkv, 256, GSMEM>>>(aq);

    kv_kernel<<<dim3(64, KV_SPLIT), 256>>>(gK, gV, gKVp, gKSp);
    kv_reduce<<<64, 256>>>(gKVp, gKSp, gKV, gKS);
    attn_kernel<<<dim3(64, 8), 256>>>(gQ, gKV, gKS, ah, al);

    // output projection (+bias)
    GemmArgs ao;
    ao.Ah[0] = ah; ao.Al[0] = al; ao.Bh[0] = woh; ao.Bl[0] = wol;
    ao.C[0] = out; ao.bias[0] = bo; ao.mode[0] = 2;
    ao.Ah[1] = ah; ao.Al[1] = al; ao.Bh[1] = woh; ao.Bl[1] = wol;
    ao.C[1] = out; ao.bias[1] = bo; ao.mode[1] = 2;
    ao.Ah[2] = ah; ao.Al[2] = al; ao.Bh[2] = woh; ao.Bl[2] = wol;
    ao.C[2] = out; ao.bias[2] = bo; ao.mode[2] = 2;

    dim3 go(DD / TN, MM / TM, 1);     // (8, 128, 1)
    gemm_mma<<<go, 256, GSMEM>>>(ao);
}

// round 7
// speedup vs baseline: 1.6349x; 1.4477x over previous
#include <cuda_runtime.h>
#include <cuda_fp16.h>
#include <cstdint>
#include <cstddef>

// Problem constants
#define BB 4
#define SS 4096
#define DD 1024
#define HH 16
#define DK 64
#define MM (BB * SS)          // 16384

// ---------------- scratch (device globals; no runtime allocation) ----------
__device__ float g_Q[(size_t)MM * DD];
__device__ float g_K[(size_t)MM * DD];
__device__ float g_V[(size_t)MM * DD];

__device__ __half g_q16[(size_t)MM * DD];
__device__ __half g_k16[(size_t)MM * DD];
__device__ __half g_v16[(size_t)MM * DD];
__device__ __half g_a16[(size_t)MM * DD];

__device__ __half g_wq_hi[(size_t)DD * DD];
__device__ __half g_wq_lo[(size_t)DD * DD];
__device__ __half g_wk_hi[(size_t)DD * DD];
__device__ __half g_wk_lo[(size_t)DD * DD];
__device__ __half g_wv_hi[(size_t)DD * DD];
__device__ __half g_wv_lo[(size_t)DD * DD];
__device__ __half g_wo_hi[(size_t)DD * DD];
__device__ __half g_wo_lo[(size_t)DD * DD];

#define KV_SPLIT 32
__device__ float g_KVp[(size_t)KV_SPLIT * 64 * DK * DK];
__device__ float g_KSp[(size_t)KV_SPLIT * 64 * DK];
__device__ float g_KV[(size_t)64 * DK * DK];
__device__ float g_KS[(size_t)64 * DK];

// ============================ PTX helpers ==================================
__device__ __forceinline__ uint32_t s2u(const void* p) {
    uint32_t a;
    asm("{ .reg .u64 t; cvta.to.shared.u64 t, %1; cvt.u32.u64 %0, t; }"
        : "=r"(a) : "l"(p));
    return a;
}

__device__ __forceinline__ void cp16(uint32_t dst, const void* src) {
    asm volatile("cp.async.cg.shared.global [%0], [%1], 16;"
                 :: "r"(dst), "l"(src) : "memory");
}

#define LDSM4(r, addr)                                                         \
    asm volatile("ldmatrix.sync.aligned.m8n8.x4.shared.b16 "                   \
                 "{%0,%1,%2,%3}, [%4];"                                        \
                 : "=r"((r)[0]), "=r"((r)[1]), "=r"((r)[2]), "=r"((r)[3])      \
                 : "r"(addr))

#define MMA16816(d, a, b)                                                      \
    asm volatile("mma.sync.aligned.m16n8k16.row.col.f32.f16.f16.f32 "          \
                 "{%0,%1,%2,%3}, {%4,%5,%6,%7}, {%8,%9}, {%0,%1,%2,%3};"       \
                 : "+f"((d)[0]), "+f"((d)[1]), "+f"((d)[2]), "+f"((d)[3])      \
                 : "r"((a)[0]), "r"((a)[1]), "r"((a)[2]), "r"((a)[3]),         \
                   "r"((b)[0]), "r"((b)[1]))

// ============================ conversion kernels ===========================
// fp32 -> fp16 cast (activations), 4 independent chains per thread
__global__ void __launch_bounds__(256)
round_fp16(const float* __restrict__ x, __half* __restrict__ y, int n4)
{
    const int stride = n4 >> 2;
    int i0 = blockIdx.x * blockDim.x + threadIdx.x;
    if (i0 >= stride) return;
    float4 v[4];
#pragma unroll
    for (int c = 0; c < 4; c++) v[c] = ((const float4*)x)[i0 + c * stride];
#pragma unroll
    for (int c = 0; c < 4; c++) {
        const int i = i0 + c * stride;
        __half2* yp = (__half2*)y;
        yp[2 * i]     = __floats2half2_rn(v[c].x, v[c].y);
        yp[2 * i + 1] = __floats2half2_rn(v[c].z, v[c].w);
    }
}

// fp32 -> (hi, lo) fp16 pair (weights)
__global__ void __launch_bounds__(256)
split_fp16(const float* __restrict__ x, __half* __restrict__ hi,
           __half* __restrict__ lo, int n4)
{
    int i = blockIdx.x * blockDim.x + threadIdx.x;
    if (i >= n4) return;
    float4 v = ((const float4*)x)[i];
    float f[4] = {v.x, v.y, v.z, v.w};
    __half h[4], l[4];
#pragma unroll
    for (int j = 0; j < 4; j++) {
        h[j] = __float2half_rn(f[j]);
        l[j] = __float2half_rn(f[j] - __half2float(h[j]));
    }
    __half2* hp = (__half2*)hi;
    __half2* lp = (__half2*)lo;
    hp[2 * i]     = __halves2half2(h[0], h[1]);
    hp[2 * i + 1] = __halves2half2(h[2], h[3]);
    lp[2 * i]     = __halves2half2(l[0], l[1]);
    lp[2 * i + 1] = __halves2half2(l[2], l[3]);
}

// ============================ mma.sync GEMM ================================
// C[m,n] = sum_k A[m,k]*W[n,k]. A single-rounded fp16; W split fp16 hi/lo.
// D = A*Wh + A*Wl  (2 MMA products, full W precision, A rounding ~1.5e-4)
// mode: 0 = plain, 1 = phi (elu+1), 2 = +bias
#define TM 128
#define TN 128
#define BKE 64                      // k elems per stage
#define KCH (DD / BKE)              // 16 chunks
#define RS 144                      // smem row stride bytes (128 data + 16 pad)
#define SPLIT_B (128 * RS)          // 18432
#define STAGE_B (3 * SPLIT_B)       // 55296 (A, Wh, Wl)
#define GSMEM (2 * STAGE_B)         // 110592

struct GemmArgs {
    const __half* A[3];
    const __half* Bh[3];
    const __half* Bl[3];
    const float* bias[3];
    float* C[3];
    int mode[3];
};

__global__ void __launch_bounds__(256)
gemm_mma(GemmArgs p)
{
    extern __shared__ char smem[];
    const uint32_t sb = s2u(smem);
    const int tid = threadIdx.x;
    const int lane = tid & 31;
    const int warp = tid >> 5;
    const int wm = warp & 3;        // 32-row slab
    const int wn = warp >> 2;       // 64-col slab
    const int z = blockIdx.z;
    const int bm = blockIdx.y * TM;
    const int bn = blockIdx.x * TN;
    const int mode = p.mode[z];

    const __half* gsrc[3];
    gsrc[0] = p.A[z]  + (size_t)bm * DD;
    gsrc[1] = p.Bh[z] + (size_t)bn * DD;
    gsrc[2] = p.Bl[z] + (size_t)bn * DD;

    auto produce = [&](int c) {
        const uint32_t st = sb + (uint32_t)(c & 1) * STAGE_B;
#pragma unroll
        for (int it = 0; it < 12; it++) {
            const int li  = it * 256 + tid;     // 0..3071
            const int s   = li >> 10;           // split 0..2
            const int idx = li & 1023;
            const int r   = idx >> 3;           // row 0..127
            const int seg = idx & 7;            // 16B segment
            cp16(st + (uint32_t)(s * SPLIT_B + r * RS + seg * 16),
                 gsrc[s] + (size_t)r * DD + c * BKE + seg * 8);
        }
        asm volatile("cp.async.commit_group;" ::: "memory");
    };

    float acc[2][8][4];
#pragma unroll
    for (int i = 0; i < 2; i++)
#pragma unroll
        for (int j = 0; j < 8; j++)
#pragma unroll
            for (int k = 0; k < 4; k++) acc[i][j][k] = 0.0f;

    produce(0);

    for (int c = 0; c < KCH; c++) {
        asm volatile("cp.async.wait_group 0;" ::: "memory");
        __syncthreads();
        if (c + 1 < KCH) produce(c + 1);   // overlaps entire chunk compute

        const uint32_t st = sb + (uint32_t)(c & 1) * STAGE_B;
#pragma unroll
        for (int step = 0; step < 4; step++) {
            uint32_t ah[2][4], bh[8][2], bl[8][2];
#pragma unroll
            for (int mt = 0; mt < 2; mt++) {
                const int row = wm * 32 + mt * 16 + (lane & 15);
                const uint32_t off =
                    (uint32_t)(row * RS + step * 32 + ((lane >> 4) & 1) * 16);
                LDSM4(ah[mt], st + off);
            }
#pragma unroll
            for (int nt2 = 0; nt2 < 4; nt2++) {
                // W tile is [N,K] row-major (k contiguous) -> non-trans ldmatrix
                const int nrow = wn * 64 + nt2 * 16 + (lane & 7) + ((lane >> 4) & 1) * 8;
                const uint32_t off =
                    (uint32_t)(nrow * RS + step * 32 + ((lane >> 3) & 1) * 16);
                uint32_t r[4];
                LDSM4(r, st + SPLIT_B + off);
                bh[nt2 * 2][0] = r[0]; bh[nt2 * 2][1] = r[1];
                bh[nt2 * 2 + 1][0] = r[2]; bh[nt2 * 2 + 1][1] = r[3];
                LDSM4(r, st + 2 * SPLIT_B + off);
                bl[nt2 * 2][0] = r[0]; bl[nt2 * 2][1] = r[1];
                bl[nt2 * 2 + 1][0] = r[2]; bl[nt2 * 2 + 1][1] = r[3];
            }
            // product-major: same accumulator touched every 16 MMAs
#pragma unroll
            for (int mt = 0; mt < 2; mt++)
#pragma unroll
                for (int nt = 0; nt < 8; nt++)
                    MMA16816(acc[mt][nt], ah[mt], bh[nt]);
#pragma unroll
            for (int mt = 0; mt < 2; mt++)
#pragma unroll
                for (int nt = 0; nt < 8; nt++)
                    MMA16816(acc[mt][nt], ah[mt], bl[nt]);
        }
    }

    // epilogue
    float* C = p.C[z];
    const int gr = lane >> 2;        // 0..7
    const int gc = (lane & 3) * 2;   // 0,2,4,6
#pragma unroll
    for (int mt = 0; mt < 2; mt++) {
#pragma unroll
        for (int nt = 0; nt < 8; nt++) {
            const int row0 = bm + wm * 32 + mt * 16 + gr;
            const int col  = bn + wn * 64 + nt * 8 + gc;
            float v[4] = {acc[mt][nt][0], acc[mt][nt][1],
                          acc[mt][nt][2], acc[mt][nt][3]};
            if (mode == 1) {
#pragma unroll
                for (int j = 0; j < 4; j++)
                    v[j] = (v[j] > 0.0f) ? (v[j] + 1.0f) : expf(v[j]);
            } else if (mode == 2) {
                const float b0 = p.bias[z][col], b1 = p.bias[z][col + 1];
                v[0] += b0; v[1] += b1; v[2] += b0; v[3] += b1;
            }
            float2 p0; p0.x = v[0]; p0.y = v[1];
            float2 p1; p1.x = v[2]; p1.y = v[3];
            *(float2*)(C + (size_t)row0 * DD + col) = p0;
            *(float2*)(C + (size_t)(row0 + 8) * DD + col) = p1;
        }
    }
}

// ---------------- KV accumulation: KV[bh] = sum_s k(s) outer v(s) ----------
__global__ void __launch_bounds__(256)
kv_kernel(const float* __restrict__ Kp, const float* __restrict__ Vp,
          float* __restrict__ KVp, float* __restrict__ KSp)
{
    const int bh = blockIdx.x;          // 0..63
    const int sp = blockIdx.y;          // 0..KV_SPLIT-1
    const int b = bh >> 4, h = bh & 15;
    const int tid = threadIdx.x;
    const int tx = tid & 15;
    const int ty = tid >> 4;

    __shared__ float ks[8][68];
    __shared__ float vs[8][68];

    float acc[4][4];
#pragma unroll
    for (int i = 0; i < 4; i++)
#pragma unroll
        for (int j = 0; j < 4; j++) acc[i][j] = 0.0f;
    float kacc = 0.0f;

    const int sPer = SS / KV_SPLIT;     // 128
    const int sBase = sp * sPer;

    const int lrow = (tid & 127) >> 4;  // 0..7
    const int lseg = tid & 15;          // 0..15

    for (int s0 = 0; s0 < sPer; s0 += 8) {
        const size_t gaddr =
            ((size_t)(b * SS + sBase + s0 + lrow)) * DD + h * DK + lseg * 4;
        if (tid < 128)
            *(float4*)&ks[lrow][lseg * 4] = *(const float4*)(Kp + gaddr);
        else
            *(float4*)&vs[lrow][lseg * 4] = *(const float4*)(Vp + gaddr);
        __syncthreads();

        if (tid < 64) {
#pragma unroll
            for (int j = 0; j < 8; j++) kacc += ks[j][tid];
        }
#pragma unroll
        for (int j = 0; j < 8; j++) {
            float4 av = *(const float4*)&ks[j][ty * 4];
            float4 bv = *(const float4*)&vs[j][tx * 4];
            float a[4] = {av.x, av.y, av.z, av.w};
            float c[4] = {bv.x, bv.y, bv.z, bv.w};
#pragma unroll
            for (int i = 0; i < 4; i++)
#pragma unroll
                for (int jj = 0; jj < 4; jj++)
                    acc[i][jj] += a[i] * c[jj];
        }
        __syncthreads();
    }

    float* outp = KVp + ((size_t)(sp * 64 + bh)) * (DK * DK);
#pragma unroll
    for (int i = 0; i < 4; i++)
#pragma unroll
        for (int jj = 0; jj < 4; jj++)
            outp[(ty * 4 + i) * DK + tx * 4 + jj] = acc[i][jj];

    if (tid < 64)
        KSp[((size_t)(sp * 64 + bh)) * DK + tid] = kacc;
}

__global__ void kv_reduce(const float* __restrict__ KVp, const float* __restrict__ KSp,
                          float* __restrict__ KV, float* __restrict__ KS)
{
    const int bh = blockIdx.x;
    const int tid = threadIdx.x;
    for (int e = tid; e < DK * DK; e += 256) {
        float s = 0.0f;
#pragma unroll
        for (int r = 0; r < KV_SPLIT; r++)
            s += KVp[((size_t)(r * 64 + bh)) * (DK * DK) + e];
        KV[(size_t)bh * (DK * DK) + e] = s;
    }
    if (tid < DK) {
        float s = 0.0f;
#pragma unroll
        for (int r = 0; r < KV_SPLIT; r++)
            s += KSp[((size_t)(r * 64 + bh)) * DK + tid];
        KS[(size_t)bh * DK + tid] = s;
    }
}

// ---------------- attention normalize -> fp16 output -----------------------
// Warp-autonomous: per-warp q buffers, __syncwarp only, 8 rows in flight.
__global__ void __launch_bounds__(256)
attn_kernel(const float* __restrict__ Q, const float* __restrict__ KV,
            const float* __restrict__ KS, __half* __restrict__ A16)
{
    const int bh = blockIdx.x;          // 0..63
    const int sc = blockIdx.y;          // 0..7 (512 rows per block)
    const int b = bh >> 4, h = bh & 15;
    const int tid = threadIdx.x;
    const int w = tid >> 5, l = tid & 31;

    __shared__ float KVs[DK * DK];
    __shared__ float KSs[DK];
    __shared__ float qb[8][8][64];      // [warp][row][dk]

    for (int i = tid; i < (DK * DK) / 4; i += 256)
        ((float4*)KVs)[i] = ((const float4*)(KV + (size_t)bh * DK * DK))[i];
    if (tid < DK) KSs[tid] = KS[(size_t)bh * DK + tid];
    __syncthreads();

    const size_t qbase = ((size_t)(b * SS) + sc * 512 + w * 64) * DD + h * DK;

    for (int g = 0; g < 8; g++) {
        const float* qrow = Q + qbase + (size_t)(g * 8) * DD;
#pragma unroll
        for (int t = 0; t < 4; t++) {
            const int idx = l + t * 32;           // 0..127
            const int r = idx >> 4, seg = idx & 15;
            *(float4*)&qb[w][r][seg * 4] =
                *(const float4*)(qrow + (size_t)r * DD + seg * 4);
        }
        __syncwarp();

        float n0[8], n1[8], dn[8];
#pragma unroll
        for (int r = 0; r < 8; r++) { n0[r] = 0.f; n1[r] = 0.f; dn[r] = 0.f; }
#pragma unroll
        for (int dk = 0; dk < DK; dk++) {
            const float kv0 = KVs[dk * DK + l];
            const float kv1 = KVs[dk * DK + l + 32];
            const float ksv = KSs[dk];
#pragma unroll
            for (int r = 0; r < 8; r++) {
                const float q = qb[w][r][dk];
                n0[r] += q * kv0;
                n1[r] += q * kv1;
                dn[r] += q * ksv;
            }
        }
#pragma unroll
        for (int r = 0; r < 8; r++) {
            const size_t orow = qbase + (size_t)(g * 8 + r) * DD;
            const float inv = 1.0f / (dn[r] + 1e-6f);
            A16[orow + l]      = __float2half_rn(n0[r] * inv);
            A16[orow + l + 32] = __float2half_rn(n1[r] * inv);
        }
        __syncwarp();
    }
}

// ---------------- launch ---------------------------------------------------
extern "C" void kernel_launch(void* const* d_in, const int* in_sizes, int n_in,
                              void* d_out, int out_size)
{
    const float* query = (const float*)d_in[0];
    const float* key   = (const float*)d_in[1];
    const float* value = (const float*)d_in[2];
    const float* Wq    = (const float*)d_in[3];
    const float* Wk    = (const float*)d_in[4];
    const float* Wv    = (const float*)d_in[5];
    const float* Wo    = (const float*)d_in[6];
    const float* bo    = (const float*)d_in[7];
    float* out = (float*)d_out;

    float *gQ, *gK, *gV, *gKVp, *gKSp, *gKV, *gKS;
    __half *q16, *k16, *v16, *a16;
    __half *wqh, *wql, *wkh, *wkl, *wvh, *wvl, *woh, *wol;
    cudaGetSymbolAddress((void**)&gQ,  g_Q);
    cudaGetSymbolAddress((void**)&gK,  g_K);
    cudaGetSymbolAddress((void**)&gV,  g_V);
    cudaGetSymbolAddress((void**)&gKVp, g_KVp);
    cudaGetSymbolAddress((void**)&gKSp, g_KSp);
    cudaGetSymbolAddress((void**)&gKV, g_KV);
    cudaGetSymbolAddress((void**)&gKS, g_KS);
    cudaGetSymbolAddress((void**)&q16, g_q16);
    cudaGetSymbolAddress((void**)&k16, g_k16);
    cudaGetSymbolAddress((void**)&v16, g_v16);
    cudaGetSymbolAddress((void**)&a16, g_a16);
    cudaGetSymbolAddress((void**)&wqh, g_wq_hi);
    cudaGetSymbolAddress((void**)&wql, g_wq_lo);
    cudaGetSymbolAddress((void**)&wkh, g_wk_hi);
    cudaGetSymbolAddress((void**)&wkl, g_wk_lo);
    cudaGetSymbolAddress((void**)&wvh, g_wv_hi);
    cudaGetSymbolAddress((void**)&wvl, g_wv_lo);
    cudaGetSymbolAddress((void**)&woh, g_wo_hi);
    cudaGetSymbolAddress((void**)&wol, g_wo_lo);

    cudaFuncSetAttribute(gemm_mma, cudaFuncAttributeMaxDynamicSharedMemorySize,
                         GSMEM);

    const int nAct4 = (MM * DD) / 4;
    const int nW4   = (DD * DD) / 4;
    round_fp16<<<nAct4 / 4 / 256, 256>>>(query, q16, nAct4);
    round_fp16<<<nAct4 / 4 / 256, 256>>>(key,   k16, nAct4);
    round_fp16<<<nAct4 / 4 / 256, 256>>>(value, v16, nAct4);
    split_fp16<<<nW4 / 256, 256>>>(Wq, wqh, wql, nW4);
    split_fp16<<<nW4 / 256, 256>>>(Wk, wkh, wkl, nW4);
    split_fp16<<<nW4 / 256, 256>>>(Wv, wvh, wvl, nW4);
    split_fp16<<<nW4 / 256, 256>>>(Wo, woh, wol, nW4);

    // fused Q/K/V projections (z = 0,1,2)
    GemmArgs aq;
    aq.A[0] = q16; aq.Bh[0] = wqh; aq.Bl[0] = wql;
    aq.C[0] = gQ; aq.bias[0] = bo; aq.mode[0] = 1;
    aq.A[1] = k16; aq.Bh[1] = wkh; aq.Bl[1] = wkl;
    aq.C[1] = gK; aq.bias[1] = bo; aq.mode[1] = 1;
    aq.A[2] = v16; aq.Bh[2] = wvh; aq.Bl[2] = wvl;
    aq.C[2] = gV; aq.bias[2] = bo; aq.mode[2] = 0;

    dim3 gqkv(DD / TN, MM / TM, 3);   // (8, 128, 3)
    gemm_mma<<<gqkv, 256, GSMEM>>>(aq);

    kv_kernel<<<dim3(64, KV_SPLIT), 256>>>(gK, gV, gKVp, gKSp);
    kv_reduce<<<64, 256>>>(gKVp, gKSp, gKV, gKS);
    attn_kernel<<<dim3(64, 8), 256>>>(gQ, gKV, gKS, a16);

    // output projection (+bias)
    GemmArgs ao;
    ao.A[0] = a16; ao.Bh[0] = woh; ao.Bl[0] = wol;
    ao.C[0] = out; ao.bias[0] = bo; ao.mode[0] = 2;
    ao.A[1] = a16; ao.Bh[1] = woh; ao.Bl[1] = wol;
    ao.C[1] = out; ao.bias[1] = bo; ao.mode[1] = 2;
    ao.A[2] = a16; ao.Bh[2] = woh; ao.Bl[2] = wol;
    ao.C[2] = out; ao.bias[2] = bo; ao.mode[2] = 2;

    dim3 go(DD / TN, MM / TM, 1);     // (8, 128, 1)
    gemm_mma<<<go, 256, GSMEM>>>(ao);
}

// round 8
// speedup vs baseline: 2.2939x; 1.4031x over previous
#include <cuda_runtime.h>
#include <cuda_fp16.h>
#include <cstdint>
#include <cstddef>

// Problem constants
#define BB 4
#define SS 4096
#define DD 1024
#define HH 16
#define DK 64
#define MM (BB * SS)          // 16384

// ---------------- scratch (device globals; no runtime allocation) ----------
__device__ float g_Q[(size_t)MM * DD];
__device__ float g_K[(size_t)MM * DD];
__device__ float g_V[(size_t)MM * DD];

__device__ __half g_q16[(size_t)MM * DD];
__device__ __half g_k16[(size_t)MM * DD];
__device__ __half g_v16[(size_t)MM * DD];
__device__ __half g_a16[(size_t)MM * DD];

__device__ __half g_wq16[(size_t)DD * DD];
__device__ __half g_wk16[(size_t)DD * DD];
__device__ __half g_wv16[(size_t)DD * DD];
__device__ __half g_wo16[(size_t)DD * DD];

#define KV_SPLIT 32
__device__ float g_KVp[(size_t)KV_SPLIT * 64 * DK * DK];
__device__ float g_KSp[(size_t)KV_SPLIT * 64 * DK];
__device__ float g_KV[(size_t)64 * DK * DK];
__device__ float g_KS[(size_t)64 * DK];

// ============================ PTX helpers ==================================
__device__ __forceinline__ uint32_t s2u(const void* p) {
    uint32_t a;
    asm("{ .reg .u64 t; cvta.to.shared.u64 t, %1; cvt.u32.u64 %0, t; }"
        : "=r"(a) : "l"(p));
    return a;
}

__device__ __forceinline__ void cp16(uint32_t dst, const void* src) {
    asm volatile("cp.async.cg.shared.global [%0], [%1], 16;"
                 :: "r"(dst), "l"(src) : "memory");
}

#define LDSM4(r, addr)                                                         \
    asm volatile("ldmatrix.sync.aligned.m8n8.x4.shared.b16 "                   \
                 "{%0,%1,%2,%3}, [%4];"                                        \
                 : "=r"((r)[0]), "=r"((r)[1]), "=r"((r)[2]), "=r"((r)[3])      \
                 : "r"(addr))

#define MMA16816(d, a, b)                                                      \
    asm volatile("mma.sync.aligned.m16n8k16.row.col.f32.f16.f16.f32 "          \
                 "{%0,%1,%2,%3}, {%4,%5,%6,%7}, {%8,%9}, {%0,%1,%2,%3};"       \
                 : "+f"((d)[0]), "+f"((d)[1]), "+f"((d)[2]), "+f"((d)[3])      \
                 : "r"((a)[0]), "r"((a)[1]), "r"((a)[2]), "r"((a)[3]),         \
                   "r"((b)[0]), "r"((b)[1]))

// ============================ conversion kernel ============================
// fp32 -> fp16 cast, 4 independent chains per thread (MLP=4)
__global__ void __launch_bounds__(256)
round_fp16(const float* __restrict__ x, __half* __restrict__ y, int n4)
{
    const int stride = n4 >> 2;
    int i0 = blockIdx.x * blockDim.x + threadIdx.x;
    if (i0 >= stride) return;
    float4 v[4];
#pragma unroll
    for (int c = 0; c < 4; c++) v[c] = ((const float4*)x)[i0 + c * stride];
#pragma unroll
    for (int c = 0; c < 4; c++) {
        const int i = i0 + c * stride;
        __half2* yp = (__half2*)y;
        yp[2 * i]     = __floats2half2_rn(v[c].x, v[c].y);
        yp[2 * i + 1] = __floats2half2_rn(v[c].z, v[c].w);
    }
}

// ============================ mma.sync GEMM ================================
// C[m,n] = sum_k A[m,k]*W[n,k]. A and W single-rounded fp16, fp32 accumulate.
// mode: 0 = plain, 1 = phi (elu+1), 2 = +bias
#define TM 128
#define TN 128
#define BKE 64                      // k elems per stage
#define KCH (DD / BKE)              // 16 chunks
#define RS 144                      // smem row stride bytes (128 data + 16 pad)
#define SPLIT_B (128 * RS)          // 18432
#define STAGE_B (2 * SPLIT_B)       // 36864 (A, W)
#define GSMEM (2 * STAGE_B)         // 73728 -> 2 CTAs/SM

struct GemmArgs {
    const __half* A[3];
    const __half* B[3];
    const float* bias[3];
    float* C[3];
    int mode[3];
};

__global__ void __launch_bounds__(256)
gemm_mma(GemmArgs p)
{
    extern __shared__ char smem[];
    const uint32_t sb = s2u(smem);
    const int tid = threadIdx.x;
    const int lane = tid & 31;
    const int warp = tid >> 5;
    const int wm = warp & 3;        // 32-row slab
    const int wn = warp >> 2;       // 64-col slab
    const int z = blockIdx.z;
    const int bm = blockIdx.y * TM;
    const int bn = blockIdx.x * TN;
    const int mode = p.mode[z];

    const __half* gsrc[2];
    gsrc[0] = p.A[z] + (size_t)bm * DD;
    gsrc[1] = p.B[z] + (size_t)bn * DD;

    auto produce = [&](int c) {
        const uint32_t st = sb + (uint32_t)(c & 1) * STAGE_B;
#pragma unroll
        for (int it = 0; it < 8; it++) {
            const int li  = it * 256 + tid;     // 0..2047
            const int s   = li >> 10;           // split 0..1
            const int idx = li & 1023;
            const int r   = idx >> 3;           // row 0..127
            const int seg = idx & 7;            // 16B segment
            cp16(st + (uint32_t)(s * SPLIT_B + r * RS + seg * 16),
                 gsrc[s] + (size_t)r * DD + c * BKE + seg * 8);
        }
        asm volatile("cp.async.commit_group;" ::: "memory");
    };

    float acc[2][8][4];
#pragma unroll
    for (int i = 0; i < 2; i++)
#pragma unroll
        for (int j = 0; j < 8; j++)
#pragma unroll
            for (int k = 0; k < 4; k++) acc[i][j][k] = 0.0f;

    produce(0);

    for (int c = 0; c < KCH; c++) {
        asm volatile("cp.async.wait_group 0;" ::: "memory");
        __syncthreads();
        if (c + 1 < KCH) produce(c + 1);   // overlaps entire chunk compute

        const uint32_t st = sb + (uint32_t)(c & 1) * STAGE_B;
#pragma unroll
        for (int step = 0; step < 4; step++) {
            uint32_t ah[2][4], bh[8][2];
#pragma unroll
            for (int mt = 0; mt < 2; mt++) {
                const int row = wm * 32 + mt * 16 + (lane & 15);
                const uint32_t off =
                    (uint32_t)(row * RS + step * 32 + ((lane >> 4) & 1) * 16);
                LDSM4(ah[mt], st + off);
            }
#pragma unroll
            for (int nt2 = 0; nt2 < 4; nt2++) {
                // W tile is [N,K] row-major (k contiguous) -> non-trans ldmatrix
                const int nrow = wn * 64 + nt2 * 16 + (lane & 7) + ((lane >> 4) & 1) * 8;
                const uint32_t off =
                    (uint32_t)(nrow * RS + step * 32 + ((lane >> 3) & 1) * 16);
                uint32_t r[4];
                LDSM4(r, st + SPLIT_B + off);
                bh[nt2 * 2][0] = r[0]; bh[nt2 * 2][1] = r[1];
                bh[nt2 * 2 + 1][0] = r[2]; bh[nt2 * 2 + 1][1] = r[3];
            }
#pragma unroll
            for (int mt = 0; mt < 2; mt++)
#pragma unroll
                for (int nt = 0; nt < 8; nt++)
                    MMA16816(acc[mt][nt], ah[mt], bh[nt]);
        }
    }

    // epilogue
    float* C = p.C[z];
    const int gr = lane >> 2;        // 0..7
    const int gc = (lane & 3) * 2;   // 0,2,4,6
#pragma unroll
    for (int mt = 0; mt < 2; mt++) {
#pragma unroll
        for (int nt = 0; nt < 8; nt++) {
            const int row0 = bm + wm * 32 + mt * 16 + gr;
            const int col  = bn + wn * 64 + nt * 8 + gc;
            float v[4] = {acc[mt][nt][0], acc[mt][nt][1],
                          acc[mt][nt][2], acc[mt][nt][3]};
            if (mode == 1) {
#pragma unroll
                for (int j = 0; j < 4; j++)
                    v[j] = (v[j] > 0.0f) ? (v[j] + 1.0f) : expf(v[j]);
            } else if (mode == 2) {
                const float b0 = p.bias[z][col], b1 = p.bias[z][col + 1];
                v[0] += b0; v[1] += b1; v[2] += b0; v[3] += b1;
            }
            float2 p0; p0.x = v[0]; p0.y = v[1];
            float2 p1; p1.x = v[2]; p1.y = v[3];
            *(float2*)(C + (size_t)row0 * DD + col) = p0;
            *(float2*)(C + (size_t)(row0 + 8) * DD + col) = p1;
        }
    }
}

// ---------------- KV accumulation: KV[bh] = sum_s k(s) outer v(s) ----------
__global__ void __launch_bounds__(256)
kv_kernel(const float* __restrict__ Kp, const float* __restrict__ Vp,
          float* __restrict__ KVp, float* __restrict__ KSp)
{
    const int bh = blockIdx.x;          // 0..63
    const int sp = blockIdx.y;          // 0..KV_SPLIT-1
    const int b = bh >> 4, h = bh & 15;
    const int tid = threadIdx.x;
    const int tx = tid & 15;
    const int ty = tid >> 4;

    __shared__ float ks[8][68];
    __shared__ float vs[8][68];

    float acc[4][4];
#pragma unroll
    for (int i = 0; i < 4; i++)
#pragma unroll
        for (int j = 0; j < 4; j++) acc[i][j] = 0.0f;
    float kacc = 0.0f;

    const int sPer = SS / KV_SPLIT;     // 128
    const int sBase = sp * sPer;

    const int lrow = (tid & 127) >> 4;  // 0..7
    const int lseg = tid & 15;          // 0..15

    for (int s0 = 0; s0 < sPer; s0 += 8) {
        const size_t gaddr =
            ((size_t)(b * SS + sBase + s0 + lrow)) * DD + h * DK + lseg * 4;
        if (tid < 128)
            *(float4*)&ks[lrow][lseg * 4] = *(const float4*)(Kp + gaddr);
        else
            *(float4*)&vs[lrow][lseg * 4] = *(const float4*)(Vp + gaddr);
        __syncthreads();

        if (tid < 64) {
#pragma unroll
            for (int j = 0; j < 8; j++) kacc += ks[j][tid];
        }
#pragma unroll
        for (int j = 0; j < 8; j++) {
            float4 av = *(const float4*)&ks[j][ty * 4];
            float4 bv = *(const float4*)&vs[j][tx * 4];
            float a[4] = {av.x, av.y, av.z, av.w};
            float c[4] = {bv.x, bv.y, bv.z, bv.w};
#pragma unroll
            for (int i = 0; i < 4; i++)
#pragma unroll
                for (int jj = 0; jj < 4; jj++)
                    acc[i][jj] += a[i] * c[jj];
        }
        __syncthreads();
    }

    float* outp = KVp + ((size_t)(sp * 64 + bh)) * (DK * DK);
#pragma unroll
    for (int i = 0; i < 4; i++)
#pragma unroll
        for (int jj = 0; jj < 4; jj++)
            outp[(ty * 4 + i) * DK + tx * 4 + jj] = acc[i][jj];

    if (tid < 64)
        KSp[((size_t)(sp * 64 + bh)) * DK + tid] = kacc;
}

__global__ void kv_reduce(const float* __restrict__ KVp, const float* __restrict__ KSp,
                          float* __restrict__ KV, float* __restrict__ KS)
{
    const int bh = blockIdx.x;
    const int tid = threadIdx.x;
    for (int e = tid; e < DK * DK; e += 256) {
        float s = 0.0f;
#pragma unroll
        for (int r = 0; r < KV_SPLIT; r++)
            s += KVp[((size_t)(r * 64 + bh)) * (DK * DK) + e];
        KV[(size_t)bh * (DK * DK) + e] = s;
    }
    if (tid < DK) {
        float s = 0.0f;
#pragma unroll
        for (int r = 0; r < KV_SPLIT; r++)
            s += KSp[((size_t)(r * 64 + bh)) * DK + tid];
        KS[(size_t)bh * DK + tid] = s;
    }
}

// ---------------- attention normalize -> fp16 output -----------------------
__global__ void __launch_bounds__(256)
attn_kernel(const float* __restrict__ Q, const float* __restrict__ KV,
            const float* __restrict__ KS, __half* __restrict__ A16)
{
    const int bh = blockIdx.x;          // 0..63
    const int sc = blockIdx.y;          // 0..7 (512 rows per block)
    const int b = bh >> 4, h = bh & 15;
    const int tid = threadIdx.x;
    const int w = tid >> 5, l = tid & 31;

    __shared__ float KVs[DK * DK];
    __shared__ float KSs[DK];
    __shared__ float qb[8][8][64];      // [warp][row][dk]

    for (int i = tid; i < (DK * DK) / 4; i += 256)
        ((float4*)KVs)[i] = ((const float4*)(KV + (size_t)bh * DK * DK))[i];
    if (tid < DK) KSs[tid] = KS[(size_t)bh * DK + tid];
    __syncthreads();

    const size_t qbase = ((size_t)(b * SS) + sc * 512 + w * 64) * DD + h * DK;

    for (int g = 0; g < 8; g++) {
        const float* qrow = Q + qbase + (size_t)(g * 8) * DD;
#pragma unroll
        for (int t = 0; t < 4; t++) {
            const int idx = l + t * 32;           // 0..127
            const int r = idx >> 4, seg = idx & 15;
            *(float4*)&qb[w][r][seg * 4] =
                *(const float4*)(qrow + (size_t)r * DD + seg * 4);
        }
        __syncwarp();

        float n0[8], n1[8], dn[8];
#pragma unroll
        for (int r = 0; r < 8; r++) { n0[r] = 0.f; n1[r] = 0.f; dn[r] = 0.f; }
#pragma unroll
        for (int dk = 0; dk < DK; dk++) {
            const float kv0 = KVs[dk * DK + l];
            const float kv1 = KVs[dk * DK + l + 32];
            const float ksv = KSs[dk];
#pragma unroll
            for (int r = 0; r < 8; r++) {
                const float q = qb[w][r][dk];
                n0[r] += q * kv0;
                n1[r] += q * kv1;
                dn[r] += q * ksv;
            }
        }
#pragma unroll
        for (int r = 0; r < 8; r++) {
            const size_t orow = qbase + (size_t)(g * 8 + r) * DD;
            const float inv = 1.0f / (dn[r] + 1e-6f);
            A16[orow + l]      = __float2half_rn(n0[r] * inv);
            A16[orow + l + 32] = __float2half_rn(n1[r] * inv);
        }
        __syncwarp();
    }
}

// ---------------- launch ---------------------------------------------------
extern "C" void kernel_launch(void* const* d_in, const int* in_sizes, int n_in,
                              void* d_out, int out_size)
{
    const float* query = (const float*)d_in[0];
    const float* key   = (const float*)d_in[1];
    const float* value = (const float*)d_in[2];
    const float* Wq    = (const float*)d_in[3];
    const float* Wk    = (const float*)d_in[4];
    const float* Wv    = (const float*)d_in[5];
    const float* Wo    = (const float*)d_in[6];
    const float* bo    = (const float*)d_in[7];
    float* out = (float*)d_out;

    float *gQ, *gK, *gV, *gKVp, *gKSp, *gKV, *gKS;
    __half *q16, *k16, *v16, *a16, *wq16, *wk16, *wv16, *wo16;
    cudaGetSymbolAddress((void**)&gQ,  g_Q);
    cudaGetSymbolAddress((void**)&gK,  g_K);
    cudaGetSymbolAddress((void**)&gV,  g_V);
    cudaGetSymbolAddress((void**)&gKVp, g_KVp);
    cudaGetSymbolAddress((void**)&gKSp, g_KSp);
    cudaGetSymbolAddress((void**)&gKV, g_KV);
    cudaGetSymbolAddress((void**)&gKS, g_KS);
    cudaGetSymbolAddress((void**)&q16, g_q16);
    cudaGetSymbolAddress((void**)&k16, g_k16);
    cudaGetSymbolAddress((void**)&v16, g_v16);
    cudaGetSymbolAddress((void**)&a16, g_a16);
    cudaGetSymbolAddress((void**)&wq16, g_wq16);
    cudaGetSymbolAddress((void**)&wk16, g_wk16);
    cudaGetSymbolAddress((void**)&wv16, g_wv16);
    cudaGetSymbolAddress((void**)&wo16, g_wo16);

    cudaFuncSetAttribute(gemm_mma, cudaFuncAttributeMaxDynamicSharedMemorySize,
                         GSMEM);

    const int nAct4 = (MM * DD) / 4;
    const int nW4   = (DD * DD) / 4;
    round_fp16<<<nAct4 / 4 / 256, 256>>>(query, q16, nAct4);
    round_fp16<<<nAct4 / 4 / 256, 256>>>(key,   k16, nAct4);
    round_fp16<<<nAct4 / 4 / 256, 256>>>(value, v16, nAct4);
    round_fp16<<<nW4 / 4 / 256, 256>>>(Wq, wq16, nW4);
    round_fp16<<<nW4 / 4 / 256, 256>>>(Wk, wk16, nW4);
    round_fp16<<<nW4 / 4 / 256, 256>>>(Wv, wv16, nW4);
    round_fp16<<<nW4 / 4 / 256, 256>>>(Wo, wo16, nW4);

    // fused Q/K/V projections (z = 0,1,2)
    GemmArgs aq;
    aq.A[0] = q16; aq.B[0] = wq16; aq.C[0] = gQ; aq.bias[0] = bo; aq.mode[0] = 1;
    aq.A[1] = k16; aq.B[1] = wk16; aq.C[1] = gK; aq.bias[1] = bo; aq.mode[1] = 1;
    aq.A[2] = v16; aq.B[2] = wv16; aq.C[2] = gV; aq.bias[2] = bo; aq.mode[2] = 0;

    dim3 gqkv(DD / TN, MM / TM, 3);   // (8, 128, 3)
    gemm_mma<<<gqkv, 256, GSMEM>>>(aq);

    kv_kernel<<<dim3(64, KV_SPLIT), 256>>>(gK, gV, gKVp, gKSp);
    kv_reduce<<<64, 256>>>(gKVp, gKSp, gKV, gKS);
    attn_kernel<<<dim3(64, 8), 256>>>(gQ, gKV, gKS, a16);

    // output projection (+bias)
    GemmArgs ao;
    ao.A[0] = a16; ao.B[0] = wo16; ao.C[0] = out; ao.bias[0] = bo; ao.mode[0] = 2;
    ao.A[1] = a16; ao.B[1] = wo16; ao.C[1] = out; ao.bias[1] = bo; ao.mode[1] = 2;
    ao.A[2] = a16; ao.B[2] = wo16; ao.C[2] = out; ao.bias[2] = bo; ao.mode[2] = 2;

    dim3 go(DD / TN, MM / TM, 1);     // (8, 128, 1)
    gemm_mma<<<go, 256, GSMEM>>>(ao);
}

// round 9
// speedup vs baseline: 2.4019x; 1.0471x over previous
#include <cuda_runtime.h>
#include <cuda_fp16.h>
#include <cstdint>
#include <cstddef>

// Problem constants
#define BB 4
#define SS 4096
#define DD 1024
#define HH 16
#define DK 64
#define MM (BB * SS)          // 16384

// ---------------- scratch (device globals; no runtime allocation) ----------
__device__ float g_Q[(size_t)MM * DD];

__device__ __half g_q16[(size_t)MM * DD];
__device__ __half g_k16[(size_t)MM * DD];
__device__ __half g_v16[(size_t)MM * DD];
__device__ __half g_a16[(size_t)MM * DD];
__device__ __half g_ko16[(size_t)MM * DD];   // projected K (phi), fp16
__device__ __half g_vo16[(size_t)MM * DD];   // projected V, fp16

__device__ __half g_wq16[(size_t)DD * DD];
__device__ __half g_wk16[(size_t)DD * DD];
__device__ __half g_wv16[(size_t)DD * DD];
__device__ __half g_wo16[(size_t)DD * DD];

#define KV_SPLIT 32
__device__ float g_KVp[(size_t)KV_SPLIT * 64 * DK * DK];
__device__ float g_KSp[(size_t)KV_SPLIT * 64 * DK];
__device__ float g_KV[(size_t)64 * DK * DK];
__device__ float g_KS[(size_t)64 * DK];

// ============================ PTX helpers ==================================
__device__ __forceinline__ uint32_t s2u(const void* p) {
    uint32_t a;
    asm("{ .reg .u64 t; cvta.to.shared.u64 t, %1; cvt.u32.u64 %0, t; }"
        : "=r"(a) : "l"(p));
    return a;
}

__device__ __forceinline__ void cp16(uint32_t dst, const void* src) {
    asm volatile("cp.async.cg.shared.global [%0], [%1], 16;"
                 :: "r"(dst), "l"(src) : "memory");
}

#define LDSM4(r, addr)                                                         \
    asm volatile("ldmatrix.sync.aligned.m8n8.x4.shared.b16 "                   \
                 "{%0,%1,%2,%3}, [%4];"                                        \
                 : "=r"((r)[0]), "=r"((r)[1]), "=r"((r)[2]), "=r"((r)[3])      \
                 : "r"(addr))

#define MMA16816(d, a, b)                                                      \
    asm volatile("mma.sync.aligned.m16n8k16.row.col.f32.f16.f16.f32 "          \
                 "{%0,%1,%2,%3}, {%4,%5,%6,%7}, {%8,%9}, {%0,%1,%2,%3};"       \
                 : "+f"((d)[0]), "+f"((d)[1]), "+f"((d)[2]), "+f"((d)[3])      \
                 : "r"((a)[0]), "r"((a)[1]), "r"((a)[2]), "r"((a)[3]),         \
                   "r"((b)[0]), "r"((b)[1]))

// ============================ fused conversion =============================
// One launch converts all 7 fp32 tensors to fp16 (flat float4-unit index).
struct ConvArgs {
    const float* src[7];
    __half* dst[7];
    int start[8];          // prefix sums, float4 units
};

__global__ void __launch_bounds__(256)
conv_all(ConvArgs a)
{
    const int u = blockIdx.x * blockDim.x + threadIdx.x;
    if (u >= a.start[7]) return;
    int t = 0;
#pragma unroll
    for (int j = 1; j < 7; j++) t += (u >= a.start[j]) ? 1 : 0;
    const int i = u - a.start[t];
    float4 v = ((const float4*)a.src[t])[i];
    __half2* yp = (__half2*)a.dst[t];
    yp[2 * i]     = __floats2half2_rn(v.x, v.y);
    yp[2 * i + 1] = __floats2half2_rn(v.z, v.w);
}

// ============================ mma.sync GEMM ================================
// C[m,n] = sum_k A[m,k]*W[n,k]. A and W single-rounded fp16, fp32 accumulate.
// mode: 0 plain->f32, 1 phi->f32, 2 +bias->f32, 3 phi->f16, 4 plain->f16
#define TM 128
#define TN 128
#define BKE 64                      // k elems per stage
#define KCH (DD / BKE)              // 16 chunks
#define RS 144                      // smem row stride bytes (128 data + 16 pad)
#define SPLIT_B (128 * RS)          // 18432
#define STAGE_B (2 * SPLIT_B)       // 36864 (A, W)
#define NST 3
#define GSMEM (NST * STAGE_B)       // 110592 -> 2 CTAs/SM (221KB)

struct GemmArgs {
    const __half* A[3];
    const __half* B[3];
    const float* bias[3];
    void* C[3];
    int mode[3];
};

__global__ void __launch_bounds__(256, 2)
gemm_mma(GemmArgs p)
{
    extern __shared__ char smem[];
    const uint32_t sb = s2u(smem);
    const int tid = threadIdx.x;
    const int lane = tid & 31;
    const int warp = tid >> 5;
    const int wm = warp & 3;        // 32-row slab
    const int wn = warp >> 2;       // 64-col slab
    const int z = blockIdx.z;
    const int bm = blockIdx.y * TM;
    const int bn = blockIdx.x * TN;
    const int mode = p.mode[z];

    const __half* gsrc[2];
    gsrc[0] = p.A[z] + (size_t)bm * DD;
    gsrc[1] = p.B[z] + (size_t)bn * DD;

    auto produce = [&](int c) {
        const uint32_t st = sb + (uint32_t)(c % NST) * STAGE_B;
#pragma unroll
        for (int it = 0; it < 8; it++) {
            const int li  = it * 256 + tid;     // 0..2047
            const int s   = li >> 10;           // split 0..1
            const int idx = li & 1023;
            const int r   = idx >> 3;           // row 0..127
            const int seg = idx & 7;            // 16B segment
            cp16(st + (uint32_t)(s * SPLIT_B + r * RS + seg * 16),
                 gsrc[s] + (size_t)r * DD + c * BKE + seg * 8);
        }
        asm volatile("cp.async.commit_group;" ::: "memory");
    };

    float acc[2][8][4];
#pragma unroll
    for (int i = 0; i < 2; i++)
#pragma unroll
        for (int j = 0; j < 8; j++)
#pragma unroll
            for (int k = 0; k < 4; k++) acc[i][j][k] = 0.0f;

    produce(0);
    produce(1);

    for (int c = 0; c < KCH; c++) {
        if (c == KCH - 1)
            asm volatile("cp.async.wait_group 0;" ::: "memory");
        else
            asm volatile("cp.async.wait_group 1;" ::: "memory");
        __syncthreads();
        if (c + 2 < KCH) produce(c + 2);   // buffer (c+2)%3 freed last iter

        const uint32_t st = sb + (uint32_t)(c % NST) * STAGE_B;
#pragma unroll
        for (int step = 0; step < 4; step++) {
            uint32_t ah[2][4], bh[8][2];
#pragma unroll
            for (int mt = 0; mt < 2; mt++) {
                const int row = wm * 32 + mt * 16 + (lane & 15);
                const uint32_t off =
                    (uint32_t)(row * RS + step * 32 + ((lane >> 4) & 1) * 16);
                LDSM4(ah[mt], st + off);
            }
#pragma unroll
            for (int nt2 = 0; nt2 < 4; nt2++) {
                // W tile is [N,K] row-major (k contiguous) -> non-trans ldmatrix
                const int nrow = wn * 64 + nt2 * 16 + (lane & 7) + ((lane >> 4) & 1) * 8;
                const uint32_t off =
                    (uint32_t)(nrow * RS + step * 32 + ((lane >> 3) & 1) * 16);
                uint32_t r[4];
                LDSM4(r, st + SPLIT_B + off);
                bh[nt2 * 2][0] = r[0]; bh[nt2 * 2][1] = r[1];
                bh[nt2 * 2 + 1][0] = r[2]; bh[nt2 * 2 + 1][1] = r[3];
            }
#pragma unroll
            for (int mt = 0; mt < 2; mt++)
#pragma unroll
                for (int nt = 0; nt < 8; nt++)
                    MMA16816(acc[mt][nt], ah[mt], bh[nt]);
        }
    }

    // epilogue
    const int gr = lane >> 2;        // 0..7
    const int gc = (lane & 3) * 2;   // 0,2,4,6
#pragma unroll
    for (int mt = 0; mt < 2; mt++) {
#pragma unroll
        for (int nt = 0; nt < 8; nt++) {
            const int row0 = bm + wm * 32 + mt * 16 + gr;
            const int col  = bn + wn * 64 + nt * 8 + gc;
            float v[4] = {acc[mt][nt][0], acc[mt][nt][1],
                          acc[mt][nt][2], acc[mt][nt][3]};
            if (mode == 1 || mode == 3) {
#pragma unroll
                for (int j = 0; j < 4; j++)
                    v[j] = (v[j] > 0.0f) ? (v[j] + 1.0f) : expf(v[j]);
            } else if (mode == 2) {
                const float b0 = p.bias[z][col], b1 = p.bias[z][col + 1];
                v[0] += b0; v[1] += b1; v[2] += b0; v[3] += b1;
            }
            if (mode <= 2) {
                float* C = (float*)p.C[z];
                float2 p0; p0.x = v[0]; p0.y = v[1];
                float2 p1; p1.x = v[2]; p1.y = v[3];
                *(float2*)(C + (size_t)row0 * DD + col) = p0;
                *(float2*)(C + (size_t)(row0 + 8) * DD + col) = p1;
            } else {
                __half* C = (__half*)p.C[z];
                *(__half2*)(C + (size_t)row0 * DD + col) =
                    __floats2half2_rn(v[0], v[1]);
                *(__half2*)(C + (size_t)(row0 + 8) * DD + col) =
                    __floats2half2_rn(v[2], v[3]);
            }
        }
    }
}

// ---------------- KV accumulation: KV[bh] = sum_s k(s) outer v(s) ----------
// fp16 inputs (projected K,V), fp32 accumulate.
__global__ void __launch_bounds__(256)
kv_kernel(const __half* __restrict__ Kp, const __half* __restrict__ Vp,
          float* __restrict__ KVp, float* __restrict__ KSp)
{
    const int bh = blockIdx.x;          // 0..63
    const int sp = blockIdx.y;          // 0..KV_SPLIT-1
    const int b = bh >> 4, h = bh & 15;
    const int tid = threadIdx.x;
    const int tx = tid & 15;
    const int ty = tid >> 4;

    __shared__ float ks[8][68];
    __shared__ float vs[8][68];

    float acc[4][4];
#pragma unroll
    for (int i = 0; i < 4; i++)
#pragma unroll
        for (int j = 0; j < 4; j++) acc[i][j] = 0.0f;
    float kacc = 0.0f;

    const int sPer = SS / KV_SPLIT;     // 128
    const int sBase = sp * sPer;

    const int lrow = (tid >> 3) & 7;    // 0..7
    const int lseg = tid & 7;           // 0..7 (8 halves each)

    for (int s0 = 0; s0 < sPer; s0 += 8) {
        if (tid < 128) {
            const __half* src = (tid < 64) ? Kp : Vp;
            const size_t gaddr =
                ((size_t)(b * SS + sBase + s0 + lrow)) * DD + h * DK + lseg * 8;
            uint4 raw = *(const uint4*)(src + gaddr);
            const __half2* hp = (const __half2*)&raw;
            float2 f0 = __half22float2(hp[0]);
            float2 f1 = __half22float2(hp[1]);
            float2 f2 = __half22float2(hp[2]);
            float2 f3 = __half22float2(hp[3]);
            float* dst = (tid < 64) ? &ks[lrow][lseg * 8] : &vs[lrow][lseg * 8];
            float4 o0; o0.x = f0.x; o0.y = f0.y; o0.z = f1.x; o0.w = f1.y;
            float4 o1; o1.x = f2.x; o1.y = f2.y; o1.z = f3.x; o1.w = f3.y;
            *(float4*)(dst)     = o0;
            *(float4*)(dst + 4) = o1;
        }
        __syncthreads();

        if (tid < 64) {
#pragma unroll
            for (int j = 0; j < 8; j++) kacc += ks[j][tid];
        }
#pragma unroll
        for (int j = 0; j < 8; j++) {
            float4 av = *(const float4*)&ks[j][ty * 4];
            float4 bv = *(const float4*)&vs[j][tx * 4];
            float a[4] = {av.x, av.y, av.z, av.w};
            float c[4] = {bv.x, bv.y, bv.z, bv.w};
#pragma unroll
            for (int i = 0; i < 4; i++)
#pragma unroll
                for (int jj = 0; jj < 4; jj++)
                    acc[i][jj] += a[i] * c[jj];
        }
        __syncthreads();
    }

    float* outp = KVp + ((size_t)(sp * 64 + bh)) * (DK * DK);
#pragma unroll
    for (int i = 0; i < 4; i++)
#pragma unroll
        for (int jj = 0; jj < 4; jj++)
            outp[(ty * 4 + i) * DK + tx * 4 + jj] = acc[i][jj];

    if (tid < 64)
        KSp[((size_t)(sp * 64 + bh)) * DK + tid] = kacc;
}

__global__ void kv_reduce(const float* __restrict__ KVp, const float* __restrict__ KSp,
                          float* __restrict__ KV, float* __restrict__ KS)
{
    const int bh = blockIdx.x;
    const int tid = threadIdx.x;
    for (int e = tid; e < DK * DK; e += 256) {
        float s = 0.0f;
#pragma unroll
        for (int r = 0; r < KV_SPLIT; r++)
            s += KVp[((size_t)(r * 64 + bh)) * (DK * DK) + e];
        KV[(size_t)bh * (DK * DK) + e] = s;
    }
    if (tid < DK) {
        float s = 0.0f;
#pragma unroll
        for (int r = 0; r < KV_SPLIT; r++)
            s += KSp[((size_t)(r * 64 + bh)) * DK + tid];
        KS[(size_t)bh * DK + tid] = s;
    }
}

// ---------------- attention normalize -> fp16 output -----------------------
__global__ void __launch_bounds__(256)
attn_kernel(const float* __restrict__ Q, const float* __restrict__ KV,
            const float* __restrict__ KS, __half* __restrict__ A16)
{
    const int bh = blockIdx.x;          // 0..63
    const int sc = blockIdx.y;          // 0..7 (512 rows per block)
    const int b = bh >> 4, h = bh & 15;
    const int tid = threadIdx.x;
    const int w = tid >> 5, l = tid & 31;

    __shared__ float KVs[DK * DK];
    __shared__ float KSs[DK];
    __shared__ float qb[8][8][64];      // [warp][row][dk]

    for (int i = tid; i < (DK * DK) / 4; i += 256)
        ((float4*)KVs)[i] = ((const float4*)(KV + (size_t)bh * DK * DK))[i];
    if (tid < DK) KSs[tid] = KS[(size_t)bh * DK + tid];
    __syncthreads();

    const size_t qbase = ((size_t)(b * SS) + sc * 512 + w * 64) * DD + h * DK;

    for (int g = 0; g < 8; g++) {
        const float* qrow = Q + qbase + (size_t)(g * 8) * DD;
#pragma unroll
        for (int t = 0; t < 4; t++) {
            const int idx = l + t * 32;           // 0..127
            const int r = idx >> 4, seg = idx & 15;
            *(float4*)&qb[w][r][seg * 4] =
                *(const float4*)(qrow + (size_t)r * DD + seg * 4);
        }
        __syncwarp();

        float n0[8], n1[8], dn[8];
#pragma unroll
        for (int r = 0; r < 8; r++) { n0[r] = 0.f; n1[r] = 0.f; dn[r] = 0.f; }
#pragma unroll
        for (int dk = 0; dk < DK; dk++) {
            const float kv0 = KVs[dk * DK + l];
            const float kv1 = KVs[dk * DK + l + 32];
            const float ksv = KSs[dk];
#pragma unroll
            for (int r = 0; r < 8; r++) {
                const float q = qb[w][r][dk];
                n0[r] += q * kv0;
                n1[r] += q * kv1;
                dn[r] += q * ksv;
            }
        }
#pragma unroll
        for (int r = 0; r < 8; r++) {
            const size_t orow = qbase + (size_t)(g * 8 + r) * DD;
            const float inv = 1.0f / (dn[r] + 1e-6f);
            A16[orow + l]      = __float2half_rn(n0[r] * inv);
            A16[orow + l + 32] = __float2half_rn(n1[r] * inv);
        }
        __syncwarp();
    }
}

// ---------------- launch ---------------------------------------------------
extern "C" void kernel_launch(void* const* d_in, const int* in_sizes, int n_in,
                              void* d_out, int out_size)
{
    const float* query = (const float*)d_in[0];
    const float* key   = (const float*)d_in[1];
    const float* value = (const float*)d_in[2];
    const float* Wq    = (const float*)d_in[3];
    const float* Wk    = (const float*)d_in[4];
    const float* Wv    = (const float*)d_in[5];
    const float* Wo    = (const float*)d_in[6];
    const float* bo    = (const float*)d_in[7];
    float* out = (float*)d_out;

    float *gQ, *gKVp, *gKSp, *gKV, *gKS;
    __half *q16, *k16, *v16, *a16, *ko16, *vo16;
    __half *wq16, *wk16, *wv16, *wo16;
    cudaGetSymbolAddress((void**)&gQ,  g_Q);
    cudaGetSymbolAddress((void**)&gKVp, g_KVp);
    cudaGetSymbolAddress((void**)&gKSp, g_KSp);
    cudaGetSymbolAddress((void**)&gKV, g_KV);
    cudaGetSymbolAddress((void**)&gKS, g_KS);
    cudaGetSymbolAddress((void**)&q16, g_q16);
    cudaGetSymbolAddress((void**)&k16, g_k16);
    cudaGetSymbolAddress((void**)&v16, g_v16);
    cudaGetSymbolAddress((void**)&a16, g_a16);
    cudaGetSymbolAddress((void**)&ko16, g_ko16);
    cudaGetSymbolAddress((void**)&vo16, g_vo16);
    cudaGetSymbolAddress((void**)&wq16, g_wq16);
    cudaGetSymbolAddress((void**)&wk16, g_wk16);
    cudaGetSymbolAddress((void**)&wv16, g_wv16);
    cudaGetSymbolAddress((void**)&wo16, g_wo16);

    cudaFuncSetAttribute(gemm_mma, cudaFuncAttributeMaxDynamicSharedMemorySize,
                         GSMEM);

    // single fused conversion launch (3 activations + 4 weights)
    const int nAct4 = (MM * DD) / 4;   // 4194304
    const int nW4   = (DD * DD) / 4;   // 262144
    ConvArgs ca;
    ca.src[0] = query; ca.dst[0] = q16;
    ca.src[1] = key;   ca.dst[1] = k16;
    ca.src[2] = value; ca.dst[2] = v16;
    ca.src[3] = Wq;    ca.dst[3] = wq16;
    ca.src[4] = Wk;    ca.dst[4] = wk16;
    ca.src[5] = Wv;    ca.dst[5] = wv16;
    ca.src[6] = Wo;    ca.dst[6] = wo16;
    ca.start[0] = 0;
    ca.start[1] = nAct4;
    ca.start[2] = 2 * nAct4;
    ca.start[3] = 3 * nAct4;
    ca.start[4] = 3 * nAct4 + nW4;
    ca.start[5] = 3 * nAct4 + 2 * nW4;
    ca.start[6] = 3 * nAct4 + 3 * nW4;
    ca.start[7] = 3 * nAct4 + 4 * nW4;
    conv_all<<<(ca.start[7] + 255) / 256, 256>>>(ca);

    // fused Q/K/V projections (z = 0,1,2); K,V written directly as fp16
    GemmArgs aq;
    aq.A[0] = q16; aq.B[0] = wq16; aq.C[0] = gQ;   aq.bias[0] = bo; aq.mode[0] = 1;
    aq.A[1] = k16; aq.B[1] = wk16; aq.C[1] = ko16; aq.bias[1] = bo; aq.mode[1] = 3;
    aq.A[2] = v16; aq.B[2] = wv16; aq.C[2] = vo16; aq.bias[2] = bo; aq.mode[2] = 4;

    dim3 gqkv(DD / TN, MM / TM, 3);   // (8, 128, 3)
    gemm_mma<<<gqkv, 256, GSMEM>>>(aq);

    kv_kernel<<<dim3(64, KV_SPLIT), 256>>>(ko16, vo16, gKVp, gKSp);
    kv_reduce<<<64, 256>>>(gKVp, gKSp, gKV, gKS);
    attn_kernel<<<dim3(64, 8), 256>>>(gQ, gKV, gKS, a16);

    // output projection (+bias)
    GemmArgs ao;
    ao.A[0] = a16; ao.B[0] = wo16; ao.C[0] = out; ao.bias[0] = bo; ao.mode[0] = 2;
    ao.A[1] = a16; ao.B[1] = wo16; ao.C[1] = out; ao.bias[1] = bo; ao.mode[1] = 2;
    ao.A[2] = a16; ao.B[2] = wo16; ao.C[2] = out; ao.bias[2] = bo; ao.mode[2] = 2;

    dim3 go(DD / TN, MM / TM, 1);     // (8, 128, 1)
    gemm_mma<<<go, 256, GSMEM>>>(ao);
}

// round 10
// speedup vs baseline: 2.4332x; 1.0130x over previous
#include <cuda_runtime.h>
#include <cuda_fp16.h>
#include <cstdint>
#include <cstddef>

// Problem constants
#define BB 4
#define SS 4096
#define DD 1024
#define HH 16
#define DK 64
#define MM (BB * SS)          // 16384

// ---------------- scratch (device globals; no runtime allocation) ----------
__device__ __half g_q16[(size_t)MM * DD];
__device__ __half g_k16[(size_t)MM * DD];
__device__ __half g_v16[(size_t)MM * DD];
__device__ __half g_a16[(size_t)MM * DD];
__device__ __half g_qo16[(size_t)MM * DD];   // projected Q (phi), fp16
__device__ __half g_ko16[(size_t)MM * DD];   // projected K (phi), fp16
__device__ __half g_vo16[(size_t)MM * DD];   // projected V, fp16

__device__ __half g_wq16[(size_t)DD * DD];
__device__ __half g_wk16[(size_t)DD * DD];
__device__ __half g_wv16[(size_t)DD * DD];
__device__ __half g_wo16[(size_t)DD * DD];

#define KV_SPLIT 32
__device__ float g_KVp[(size_t)KV_SPLIT * 64 * DK * DK];
__device__ float g_KSp[(size_t)KV_SPLIT * 64 * DK];
__device__ float g_KV[(size_t)64 * DK * DK];
__device__ float g_KS[(size_t)64 * DK];

// ============================ PTX helpers ==================================
__device__ __forceinline__ uint32_t s2u(const void* p) {
    uint32_t a;
    asm("{ .reg .u64 t; cvta.to.shared.u64 t, %1; cvt.u32.u64 %0, t; }"
        : "=r"(a) : "l"(p));
    return a;
}

__device__ __forceinline__ void cp16(uint32_t dst, const void* src) {
    asm volatile("cp.async.cg.shared.global [%0], [%1], 16;"
                 :: "r"(dst), "l"(src) : "memory");
}

#define LDSM4(r, addr)                                                         \
    asm volatile("ldmatrix.sync.aligned.m8n8.x4.shared.b16 "                   \
                 "{%0,%1,%2,%3}, [%4];"                                        \
                 : "=r"((r)[0]), "=r"((r)[1]), "=r"((r)[2]), "=r"((r)[3])      \
                 : "r"(addr))

#define MMA16816(d, a, b)                                                      \
    asm volatile("mma.sync.aligned.m16n8k16.row.col.f32.f16.f16.f32 "          \
                 "{%0,%1,%2,%3}, {%4,%5,%6,%7}, {%8,%9}, {%0,%1,%2,%3};"       \
                 : "+f"((d)[0]), "+f"((d)[1]), "+f"((d)[2]), "+f"((d)[3])      \
                 : "r"((a)[0]), "r"((a)[1]), "r"((a)[2]), "r"((a)[3]),         \
                   "r"((b)[0]), "r"((b)[1]))

// ============================ fused conversion =============================
struct ConvArgs {
    const float* src[7];
    __half* dst[7];
    int start[8];          // prefix sums, float4 units
};

__global__ void __launch_bounds__(256)
conv_all(ConvArgs a)
{
    const int u = blockIdx.x * blockDim.x + threadIdx.x;
    if (u >= a.start[7]) return;
    int t = 0;
#pragma unroll
    for (int j = 1; j < 7; j++) t += (u >= a.start[j]) ? 1 : 0;
    const int i = u - a.start[t];
    float4 v = ((const float4*)a.src[t])[i];
    __half2* yp = (__half2*)a.dst[t];
    yp[2 * i]     = __floats2half2_rn(v.x, v.y);
    yp[2 * i + 1] = __floats2half2_rn(v.z, v.w);
}

// ============================ mma.sync GEMM ================================
// C[m,n] = sum_k A[m,k]*W[n,k]. A and W single-rounded fp16, fp32 accumulate.
// mode: 0 plain->f32, 1 phi->f32, 2 +bias->f32, 3 phi->f16, 4 plain->f16
#define TM 128
#define TN 128
#define BKE 64                      // k elems per stage
#define KCH (DD / BKE)              // 16 chunks
#define RS 144                      // smem row stride bytes (128 data + 16 pad)
#define SPLIT_B (128 * RS)          // 18432
#define STAGE_B (2 * SPLIT_B)       // 36864 (A, W)
#define NST 3
#define GSMEM (NST * STAGE_B)       // 110592 -> 2 CTAs/SM (221KB)

struct GemmArgs {
    const __half* A[3];
    const __half* B[3];
    const float* bias[3];
    void* C[3];
    int mode[3];
};

__global__ void __launch_bounds__(256, 2)
gemm_mma(GemmArgs p)
{
    extern __shared__ char smem[];
    const uint32_t sb = s2u(smem);
    const int tid = threadIdx.x;
    const int lane = tid & 31;
    const int warp = tid >> 5;
    const int wm = warp & 3;        // 32-row slab
    const int wn = warp >> 2;       // 64-col slab
    const int z = blockIdx.z;
    const int bm = blockIdx.y * TM;
    const int bn = blockIdx.x * TN;
    const int mode = p.mode[z];

    const __half* gsrc[2];
    gsrc[0] = p.A[z] + (size_t)bm * DD;
    gsrc[1] = p.B[z] + (size_t)bn * DD;

    auto produce = [&](int c) {
        const uint32_t st = sb + (uint32_t)(c % NST) * STAGE_B;
#pragma unroll
        for (int it = 0; it < 8; it++) {
            const int li  = it * 256 + tid;     // 0..2047
            const int s   = li >> 10;           // split 0..1
            const int idx = li & 1023;
            const int r   = idx >> 3;           // row 0..127
            const int seg = idx & 7;            // 16B segment
            cp16(st + (uint32_t)(s * SPLIT_B + r * RS + seg * 16),
                 gsrc[s] + (size_t)r * DD + c * BKE + seg * 8);
        }
        asm volatile("cp.async.commit_group;" ::: "memory");
    };

    float acc[2][8][4];
#pragma unroll
    for (int i = 0; i < 2; i++)
#pragma unroll
        for (int j = 0; j < 8; j++)
#pragma unroll
            for (int k = 0; k < 4; k++) acc[i][j][k] = 0.0f;

    produce(0);
    produce(1);

    for (int c = 0; c < KCH; c++) {
        if (c == KCH - 1)
            asm volatile("cp.async.wait_group 0;" ::: "memory");
        else
            asm volatile("cp.async.wait_group 1;" ::: "memory");
        __syncthreads();
        if (c + 2 < KCH) produce(c + 2);

        const uint32_t st = sb + (uint32_t)(c % NST) * STAGE_B;
#pragma unroll
        for (int step = 0; step < 4; step++) {
            uint32_t ah[2][4], bh[8][2];
#pragma unroll
            for (int mt = 0; mt < 2; mt++) {
                const int row = wm * 32 + mt * 16 + (lane & 15);
                const uint32_t off =
                    (uint32_t)(row * RS + step * 32 + ((lane >> 4) & 1) * 16);
                LDSM4(ah[mt], st + off);
            }
#pragma unroll
            for (int nt2 = 0; nt2 < 4; nt2++) {
                const int nrow = wn * 64 + nt2 * 16 + (lane & 7) + ((lane >> 4) & 1) * 8;
                const uint32_t off =
                    (uint32_t)(nrow * RS + step * 32 + ((lane >> 3) & 1) * 16);
                uint32_t r[4];
                LDSM4(r, st + SPLIT_B + off);
                bh[nt2 * 2][0] = r[0]; bh[nt2 * 2][1] = r[1];
                bh[nt2 * 2 + 1][0] = r[2]; bh[nt2 * 2 + 1][1] = r[3];
            }
#pragma unroll
            for (int mt = 0; mt < 2; mt++)
#pragma unroll
                for (int nt = 0; nt < 8; nt++)
                    MMA16816(acc[mt][nt], ah[mt], bh[nt]);
        }
    }

    // epilogue
    const int gr = lane >> 2;        // 0..7
    const int gc = (lane & 3) * 2;   // 0,2,4,6
#pragma unroll
    for (int mt = 0; mt < 2; mt++) {
#pragma unroll
        for (int nt = 0; nt < 8; nt++) {
            const int row0 = bm + wm * 32 + mt * 16 + gr;
            const int col  = bn + wn * 64 + nt * 8 + gc;
            float v[4] = {acc[mt][nt][0], acc[mt][nt][1],
                          acc[mt][nt][2], acc[mt][nt][3]};
            if (mode == 1 || mode == 3) {
#pragma unroll
                for (int j = 0; j < 4; j++)
                    v[j] = (v[j] > 0.0f) ? (v[j] + 1.0f) : expf(v[j]);
            } else if (mode == 2) {
                const float b0 = p.bias[z][col], b1 = p.bias[z][col + 1];
                v[0] += b0; v[1] += b1; v[2] += b0; v[3] += b1;
            }
            if (mode <= 2) {
                float* C = (float*)p.C[z];
                float2 p0; p0.x = v[0]; p0.y = v[1];
                float2 p1; p1.x = v[2]; p1.y = v[3];
                *(float2*)(C + (size_t)row0 * DD + col) = p0;
                *(float2*)(C + (size_t)(row0 + 8) * DD + col) = p1;
            } else {
                __half* C = (__half*)p.C[z];
                *(__half2*)(C + (size_t)row0 * DD + col) =
                    __floats2half2_rn(v[0], v[1]);
                *(__half2*)(C + (size_t)(row0 + 8) * DD + col) =
                    __floats2half2_rn(v[2], v[3]);
            }
        }
    }
}

// ---------------- KV accumulation: KV[bh] = sum_s k(s) outer v(s) ----------
__global__ void __launch_bounds__(256)
kv_kernel(const __half* __restrict__ Kp, const __half* __restrict__ Vp,
          float* __restrict__ KVp, float* __restrict__ KSp)
{
    const int bh = blockIdx.x;          // 0..63
    const int sp = blockIdx.y;          // 0..KV_SPLIT-1
    const int b = bh >> 4, h = bh & 15;
    const int tid = threadIdx.x;
    const int tx = tid & 15;
    const int ty = tid >> 4;

    __shared__ float ks[8][68];
    __shared__ float vs[8][68];

    float acc[4][4];
#pragma unroll
    for (int i = 0; i < 4; i++)
#pragma unroll
        for (int j = 0; j < 4; j++) acc[i][j] = 0.0f;
    float kacc = 0.0f;

    const int sPer = SS / KV_SPLIT;     // 128
    const int sBase = sp * sPer;

    const int lrow = (tid >> 3) & 7;    // 0..7
    const int lseg = tid & 7;           // 0..7 (8 halves each)

    for (int s0 = 0; s0 < sPer; s0 += 8) {
        if (tid < 128) {
            const __half* src = (tid < 64) ? Kp : Vp;
            const size_t gaddr =
                ((size_t)(b * SS + sBase + s0 + lrow)) * DD + h * DK + lseg * 8;
            uint4 raw = *(const uint4*)(src + gaddr);
            const __half2* hp = (const __half2*)&raw;
            float2 f0 = __half22float2(hp[0]);
            float2 f1 = __half22float2(hp[1]);
            float2 f2 = __half22float2(hp[2]);
            float2 f3 = __half22float2(hp[3]);
            float* dst = (tid < 64) ? &ks[lrow][lseg * 8] : &vs[lrow][lseg * 8];
            float4 o0; o0.x = f0.x; o0.y = f0.y; o0.z = f1.x; o0.w = f1.y;
            float4 o1; o1.x = f2.x; o1.y = f2.y; o1.z = f3.x; o1.w = f3.y;
            *(float4*)(dst)     = o0;
            *(float4*)(dst + 4) = o1;
        }
        __syncthreads();

        if (tid < 64) {
#pragma unroll
            for (int j = 0; j < 8; j++) kacc += ks[j][tid];
        }
#pragma unroll
        for (int j = 0; j < 8; j++) {
            float4 av = *(const float4*)&ks[j][ty * 4];
            float4 bv = *(const float4*)&vs[j][tx * 4];
            float a[4] = {av.x, av.y, av.z, av.w};
            float c[4] = {bv.x, bv.y, bv.z, bv.w};
#pragma unroll
            for (int i = 0; i < 4; i++)
#pragma unroll
                for (int jj = 0; jj < 4; jj++)
                    acc[i][jj] += a[i] * c[jj];
        }
        __syncthreads();
    }

    float* outp = KVp + ((size_t)(sp * 64 + bh)) * (DK * DK);
#pragma unroll
    for (int i = 0; i < 4; i++)
#pragma unroll
        for (int jj = 0; jj < 4; jj++)
            outp[(ty * 4 + i) * DK + tx * 4 + jj] = acc[i][jj];

    if (tid < 64)
        KSp[((size_t)(sp * 64 + bh)) * DK + tid] = kacc;
}

// ---------------- parallel reduce of KV partials ---------------------------
// grid (64, 4): each block sums 256 float4 of one head's KV + (y==0) KS.
__global__ void __launch_bounds__(256)
kv_reduce(const float* __restrict__ KVp, const float* __restrict__ KSp,
          float* __restrict__ KV, float* __restrict__ KS)
{
    const int bh = blockIdx.x;
    const int part = blockIdx.y;        // 0..3
    const int tid = threadIdx.x;
    const int e4 = part * 256 + tid;    // float4 index 0..1023

    const float4* src = (const float4*)KVp;
    float4 s; s.x = 0.f; s.y = 0.f; s.z = 0.f; s.w = 0.f;
#pragma unroll
    for (int r = 0; r < KV_SPLIT; r++) {
        float4 v = src[((size_t)(r * 64 + bh)) * (DK * DK / 4) + e4];
        s.x += v.x; s.y += v.y; s.z += v.z; s.w += v.w;
    }
    ((float4*)KV)[(size_t)bh * (DK * DK / 4) + e4] = s;

    if (part == 0 && tid < DK) {
        float t = 0.0f;
#pragma unroll
        for (int r = 0; r < KV_SPLIT; r++)
            t += KSp[((size_t)(r * 64 + bh)) * DK + tid];
        KS[(size_t)bh * DK + tid] = t;
    }
}

// ---------------- attention normalize: fp16 Q -> fp16 output ---------------
__global__ void __launch_bounds__(256)
attn_kernel(const __half* __restrict__ Q16, const float* __restrict__ KV,
            const float* __restrict__ KS, __half* __restrict__ A16)
{
    const int bh = blockIdx.x;          // 0..63
    const int sc = blockIdx.y;          // 0..7 (512 rows per block)
    const int b = bh >> 4, h = bh & 15;
    const int tid = threadIdx.x;
    const int w = tid >> 5, l = tid & 31;

    __shared__ float KVs[DK * DK];
    __shared__ float KSs[DK];
    __shared__ float qb[8][8][64];      // [warp][row][dk]

    for (int i = tid; i < (DK * DK) / 4; i += 256)
        ((float4*)KVs)[i] = ((const float4*)(KV + (size_t)bh * DK * DK))[i];
    if (tid < DK) KSs[tid] = KS[(size_t)bh * DK + tid];
    __syncthreads();

    const size_t qbase = ((size_t)(b * SS) + sc * 512 + w * 64) * DD + h * DK;

    for (int g = 0; g < 8; g++) {
        const __half* qrow = Q16 + qbase + (size_t)(g * 8) * DD;
#pragma unroll
        for (int t = 0; t < 2; t++) {
            const int idx = l + t * 32;           // 0..63
            const int r = idx >> 3, seg = idx & 7;
            uint4 raw = *(const uint4*)(qrow + (size_t)r * DD + seg * 8);
            const __half2* hp = (const __half2*)&raw;
            float2 f0 = __half22float2(hp[0]);
            float2 f1 = __half22float2(hp[1]);
            float2 f2 = __half22float2(hp[2]);
            float2 f3 = __half22float2(hp[3]);
            float* dst = &qb[w][r][seg * 8];
            float4 o0; o0.x = f0.x; o0.y = f0.y; o0.z = f1.x; o0.w = f1.y;
            float4 o1; o1.x = f2.x; o1.y = f2.y; o1.z = f3.x; o1.w = f3.y;
            *(float4*)(dst)     = o0;
            *(float4*)(dst + 4) = o1;
        }
        __syncwarp();

        float n0[8], n1[8], dn[8];
#pragma unroll
        for (int r = 0; r < 8; r++) { n0[r] = 0.f; n1[r] = 0.f; dn[r] = 0.f; }
#pragma unroll
        for (int dk = 0; dk < DK; dk++) {
            const float kv0 = KVs[dk * DK + l];
            const float kv1 = KVs[dk * DK + l + 32];
            const float ksv = KSs[dk];
#pragma unroll
            for (int r = 0; r < 8; r++) {
                const float q = qb[w][r][dk];
                n0[r] += q * kv0;
                n1[r] += q * kv1;
                dn[r] += q * ksv;
            }
        }
#pragma unroll
        for (int r = 0; r < 8; r++) {
            const size_t orow = qbase + (size_t)(g * 8 + r) * DD;
            const float inv = 1.0f / (dn[r] + 1e-6f);
            A16[orow + l]      = __float2half_rn(n0[r] * inv);
            A16[orow + l + 32] = __float2half_rn(n1[r] * inv);
        }
        __syncwarp();
    }
}

// ---------------- launch ---------------------------------------------------
extern "C" void kernel_launch(void* const* d_in, const int* in_sizes, int n_in,
                              void* d_out, int out_size)
{
    const float* query = (const float*)d_in[0];
    const float* key   = (const float*)d_in[1];
    const float* value = (const float*)d_in[2];
    const float* Wq    = (const float*)d_in[3];
    const float* Wk    = (const float*)d_in[4];
    const float* Wv    = (const float*)d_in[5];
    const float* Wo    = (const float*)d_in[6];
    const float* bo    = (const float*)d_in[7];
    float* out = (float*)d_out;

    float *gKVp, *gKSp, *gKV, *gKS;
    __half *q16, *k16, *v16, *a16, *qo16, *ko16, *vo16;
    __half *wq16, *wk16, *wv16, *wo16;
    cudaGetSymbolAddress((void**)&gKVp, g_KVp);
    cudaGetSymbolAddress((void**)&gKSp, g_KSp);
    cudaGetSymbolAddress((void**)&gKV, g_KV);
    cudaGetSymbolAddress((void**)&gKS, g_KS);
    cudaGetSymbolAddress((void**)&q16, g_q16);
    cudaGetSymbolAddress((void**)&k16, g_k16);
    cudaGetSymbolAddress((void**)&v16, g_v16);
    cudaGetSymbolAddress((void**)&a16, g_a16);
    cudaGetSymbolAddress((void**)&qo16, g_qo16);
    cudaGetSymbolAddress((void**)&ko16, g_ko16);
    cudaGetSymbolAddress((void**)&vo16, g_vo16);
    cudaGetSymbolAddress((void**)&wq16, g_wq16);
    cudaGetSymbolAddress((void**)&wk16, g_wk16);
    cudaGetSymbolAddress((void**)&wv16, g_wv16);
    cudaGetSymbolAddress((void**)&wo16, g_wo16);

    cudaFuncSetAttribute(gemm_mma, cudaFuncAttributeMaxDynamicSharedMemorySize,
                         GSMEM);

    // single fused conversion launch (3 activations + 4 weights)
    const int nAct4 = (MM * DD) / 4;   // 4194304
    const int nW4   = (DD * DD) / 4;   // 262144
    ConvArgs ca;
    ca.src[0] = query; ca.dst[0] = q16;
    ca.src[1] = key;   ca.dst[1] = k16;
    ca.src[2] = value; ca.dst[2] = v16;
    ca.src[3] = Wq;    ca.dst[3] = wq16;
    ca.src[4] = Wk;    ca.dst[4] = wk16;
    ca.src[5] = Wv;    ca.dst[5] = wv16;
    ca.src[6] = Wo;    ca.dst[6] = wo16;
    ca.start[0] = 0;
    ca.start[1] = nAct4;
    ca.start[2] = 2 * nAct4;
    ca.start[3] = 3 * nAct4;
    ca.start[4] = 3 * nAct4 + nW4;
    ca.start[5] = 3 * nAct4 + 2 * nW4;
    ca.start[6] = 3 * nAct4 + 3 * nW4;
    ca.start[7] = 3 * nAct4 + 4 * nW4;
    conv_all<<<(ca.start[7] + 255) / 256, 256>>>(ca);

    // fused Q/K/V projections; all three written directly as fp16
    GemmArgs aq;
    aq.A[0] = q16; aq.B[0] = wq16; aq.C[0] = qo16; aq.bias[0] = bo; aq.mode[0] = 3;
    aq.A[1] = k16; aq.B[1] = wk16; aq.C[1] = ko16; aq.bias[1] = bo; aq.mode[1] = 3;
    aq.A[2] = v16; aq.B[2] = wv16; aq.C[2] = vo16; aq.bias[2] = bo; aq.mode[2] = 4;

    dim3 gqkv(DD / TN, MM / TM, 3);   // (8, 128, 3)
    gemm_mma<<<gqkv, 256, GSMEM>>>(aq);

    kv_kernel<<<dim3(64, KV_SPLIT), 256>>>(ko16, vo16, gKVp, gKSp);
    kv_reduce<<<dim3(64, 4), 256>>>(gKVp, gKSp, gKV, gKS);
    attn_kernel<<<dim3(64, 8), 256>>>(qo16, gKV, gKS, a16);

    // output projection (+bias)
    GemmArgs ao;
    ao.A[0] = a16; ao.B[0] = wo16; ao.C[0] = out; ao.bias[0] = bo; ao.mode[0] = 2;
    ao.A[1] = a16; ao.B[1] = wo16; ao.C[1] = out; ao.bias[1] = bo; ao.mode[1] = 2;
    ao.A[2] = a16; ao.B[2] = wo16; ao.C[2] = out; ao.bias[2] = bo; ao.mode[2] = 2;

    dim3 go(DD / TN, MM / TM, 1);     // (8, 128, 1)
    gemm_mma<<<go, 256, GSMEM>>>(ao);
}